// round 11
// baseline (speedup 1.0000x reference)
#include <cuda_runtime.h>
#include <cuda_bf16.h>
#include <math.h>
#include <stdint.h>

// ---------------------------------------------------------------------------
// Swin block: GEMMs + attention via mma.sync bf16 (fp32 accum).
// BN=256 warp-tile GEMMs (64x64/warp); LN2 fused into proj epilogue.
// B=32, H=W=56, DIM=256, HEADS=8, WS=7, SHIFT=3, N=49, NW=64, HEAD_DIM=32.
// ---------------------------------------------------------------------------

#define TOK      100352
#define DIM      256
#define HIDDEN   1024
#define QKVDIM   768
#define HEADS    8
#define HEAD_DIM 32
#define NTOK     49
#define HW       3136
#define SHIFT    3

typedef __nv_bfloat16 bf16;

// ------------------------- scratch (device globals) ------------------------
__device__ __align__(16) bf16  g_hwin_b[(size_t)TOK * DIM];
__device__ __align__(16) bf16  g_qkv_b [(size_t)TOK * QKVDIM];
__device__ __align__(16) bf16  g_attn_b[(size_t)TOK * DIM];
__device__ __align__(16) float g_x2    [(size_t)TOK * DIM];
__device__ __align__(16) bf16  g_h2_b  [(size_t)TOK * DIM];
__device__ __align__(16) bf16  g_hbuf_b[(size_t)TOK * HIDDEN];
__device__ __align__(16) bf16  g_wqkv_b [QKVDIM * DIM];
__device__ __align__(16) bf16  g_wproj_b[DIM * DIM];
__device__ __align__(16) bf16  g_wfc1_b [HIDDEN * DIM];
__device__ __align__(16) bf16  g_wfc2_b [DIM * HIDDEN];

// ------------------------------ PTX helpers --------------------------------
__device__ __forceinline__ uint32_t smem_u32(const void* p) {
    uint32_t a;
    asm("{ .reg .u64 t; cvta.to.shared.u64 t, %1; cvt.u32.u64 %0, t; }"
        : "=r"(a) : "l"(p));
    return a;
}
__device__ __forceinline__ void cp_async16(uint32_t dst, const void* src) {
    asm volatile("cp.async.cg.shared.global [%0], [%1], 16;"
                 :: "r"(dst), "l"(src));
}
#define CP_COMMIT() asm volatile("cp.async.commit_group;")
#define CP_WAIT(n)  asm volatile("cp.async.wait_group %0;" :: "n"(n))

__device__ __forceinline__ void ldsm_x4(uint32_t& r0, uint32_t& r1,
                                        uint32_t& r2, uint32_t& r3, uint32_t a) {
    asm volatile("ldmatrix.sync.aligned.m8n8.x4.shared.b16 {%0,%1,%2,%3}, [%4];"
                 : "=r"(r0), "=r"(r1), "=r"(r2), "=r"(r3) : "r"(a));
}
__device__ __forceinline__ void ldsm_x4t(uint32_t& r0, uint32_t& r1,
                                         uint32_t& r2, uint32_t& r3, uint32_t a) {
    asm volatile("ldmatrix.sync.aligned.m8n8.x4.trans.shared.b16 {%0,%1,%2,%3}, [%4];"
                 : "=r"(r0), "=r"(r1), "=r"(r2), "=r"(r3) : "r"(a));
}
__device__ __forceinline__ void mma16816(float* d, const uint32_t* a,
                                         const uint32_t* b) {
    asm volatile(
        "mma.sync.aligned.m16n8k16.row.col.f32.bf16.bf16.f32 "
        "{%0,%1,%2,%3}, {%4,%5,%6,%7}, {%8,%9}, {%0,%1,%2,%3};"
        : "+f"(d[0]), "+f"(d[1]), "+f"(d[2]), "+f"(d[3])
        : "r"(a[0]), "r"(a[1]), "r"(a[2]), "r"(a[3]), "r"(b[0]), "r"(b[1]));
}
__device__ __forceinline__ uint32_t packbf(float lo, float hi) {
    uint32_t r;
    asm("cvt.rn.bf16x2.f32 %0, %1, %2;" : "=r"(r) : "f"(hi), "f"(lo));
    return r;
}

__device__ __forceinline__ size_t scatter_dst(int row) {
    // window-layout token index -> spatial token index (un-shift + reverse)
    int bz = row / HW;
    int r  = row - bz * HW;
    int wI = r / NTOK;
    int t2 = r - wI * NTOK;
    int wh = wI >> 3, ww = wI & 7;
    int ii = t2 / 7,  jj = t2 - (t2 / 7) * 7;
    int sh = (wh * 7 + ii + SHIFT) % 56;
    int sw = (ww * 7 + jj + SHIFT) % 56;
    return ((size_t)bz * HW + sh * 56 + sw) * DIM;
}

// ---------------------------------------------------------------------------
// LayerNorm -> bf16, gather with cyclic shift + window partition (LN1).
// ---------------------------------------------------------------------------
__global__ void ln_kernel(const float* __restrict__ in,
                          const float* __restrict__ w,
                          const float* __restrict__ b,
                          bf16* __restrict__ out)
{
    int warp = threadIdx.x >> 5;
    int lane = threadIdx.x & 31;
    int row  = blockIdx.x * 8 + warp;

    int bz = row / HW;
    int r  = row - bz * HW;
    int wI = r / NTOK;
    int t2 = r - wI * NTOK;
    int wh = wI >> 3, ww = wI & 7;
    int i  = t2 / 7,  j  = t2 - (t2 / 7) * 7;
    int sh = (wh * 7 + i + SHIFT) % 56;
    int sw = (ww * 7 + j + SHIFT) % 56;
    const float* src = in + ((size_t)bz * HW + sh * 56 + sw) * DIM;

    float v[8];
    float s = 0.f, ss = 0.f;
#pragma unroll
    for (int k = 0; k < 8; k++) {
        v[k] = src[lane + 32 * k];
        s  += v[k];
        ss += v[k] * v[k];
    }
#pragma unroll
    for (int o = 16; o; o >>= 1) {
        s  += __shfl_xor_sync(0xffffffffu, s,  o);
        ss += __shfl_xor_sync(0xffffffffu, ss, o);
    }
    float mu   = s * (1.f / DIM);
    float var  = ss * (1.f / DIM) - mu * mu;
    float rstd = rsqrtf(var + 1e-5f);

    bf16* dst = out + (size_t)row * DIM;
#pragma unroll
    for (int k = 0; k < 8; k++) {
        int c = lane + 32 * k;
        dst[c] = __float2bfloat16((v[k] - mu) * rstd * w[c] + b[c]);
    }
}

__global__ void cvt_kernel(const float* __restrict__ in,
                           bf16* __restrict__ out, int n)
{
    int i = blockIdx.x * 256 + threadIdx.x;
    if (i < n) out[i] = __float2bfloat16(in[i]);
}

// ---------------------------------------------------------------------------
// bf16 mma.sync GEMM, BM=128 BN=256 BK=32, 256 thr, warp tile 64x64.
// EPI: 0 qkv(+bias -> bf16)
//      1 proj(+bias, scatter+residual -> x2 fp32) FUSED LN2 (-> h2 bf16)
//      2 fc1(+bias, gelu -> bf16)
//      3 fc2(+bias+residual -> fp32)
// ---------------------------------------------------------------------------
#define STRIDE 40
#define A_ST   (128 * STRIDE)   // bf16 elems per A stage
#define B_ST   (256 * STRIDE)
#define SMEM_BYTES ((2 * A_ST + 2 * B_ST) * 2)

template <int EPI>
__global__ void __launch_bounds__(256)
gemm256(const bf16* __restrict__ A, const bf16* __restrict__ W,
        const float* __restrict__ bias, const float* __restrict__ extra,
        const float* __restrict__ w2, const float* __restrict__ b2,
        float* __restrict__ out, bf16* __restrict__ outb,
        int K, int Ntot)
{
    extern __shared__ char dsm[];
    bf16* As = (bf16*)dsm;
    bf16* Bs = (bf16*)dsm + 2 * A_ST;

    int tid    = threadIdx.x;
    int lane   = tid & 31;
    int wid    = tid >> 5;
    int warp_m = wid & 1;          // 2 x 64 rows
    int warp_n = wid >> 1;         // 4 x 64 cols
    int m0     = blockIdx.y * 128;
    int n0     = blockIdx.x * 256;

    int lr = tid >> 2;
    int lc = (tid & 3) << 3;

    float c[4][8][4];
#pragma unroll
    for (int i = 0; i < 4; i++)
#pragma unroll
        for (int j = 0; j < 8; j++)
#pragma unroll
            for (int k = 0; k < 4; k++) c[i][j][k] = 0.f;

    int nk = K >> 5;

    // prologue: stage 0
    {
#pragma unroll
        for (int t = 0; t < 2; t++) {
            int r = lr + t * 64;
            cp_async16(smem_u32(As + r * STRIDE + lc), A + (size_t)(m0 + r) * K + lc);
        }
#pragma unroll
        for (int t = 0; t < 4; t++) {
            int r = lr + t * 64;
            cp_async16(smem_u32(Bs + r * STRIDE + lc), W + (size_t)(n0 + r) * K + lc);
        }
        CP_COMMIT();
    }

    int a_row  = warp_m * 64 + (lane & 15);
    int a_koff = (lane >> 4) << 3;
    int b_row0 = warp_n * 64 + (lane & 7) + ((lane >> 4) << 3);
    int b_koff = ((lane >> 3) & 1) << 3;

    for (int kk = 0; kk < nk; kk++) {
        int st = kk & 1;
        if (kk + 1 < nk) {
            int kb = (kk + 1) << 5;
            int s2 = (st ^ 1);
#pragma unroll
            for (int t = 0; t < 2; t++) {
                int r = lr + t * 64;
                cp_async16(smem_u32(As + s2 * A_ST + r * STRIDE + lc),
                           A + (size_t)(m0 + r) * K + kb + lc);
            }
#pragma unroll
            for (int t = 0; t < 4; t++) {
                int r = lr + t * 64;
                cp_async16(smem_u32(Bs + s2 * B_ST + r * STRIDE + lc),
                           W + (size_t)(n0 + r) * K + kb + lc);
            }
            CP_COMMIT();
            CP_WAIT(1);
        } else {
            CP_WAIT(0);
        }
        __syncthreads();

#pragma unroll
        for (int ks = 0; ks < 2; ks++) {
            uint32_t a[4][4];
            uint32_t b[8][2];
#pragma unroll
            for (int mt = 0; mt < 4; mt++)
                ldsm_x4(a[mt][0], a[mt][1], a[mt][2], a[mt][3],
                        smem_u32(As + st * A_ST + (a_row + mt * 16) * STRIDE
                                 + ks * 16 + a_koff));
#pragma unroll
            for (int nt2 = 0; nt2 < 4; nt2++)
                ldsm_x4(b[nt2 * 2][0], b[nt2 * 2][1],
                        b[nt2 * 2 + 1][0], b[nt2 * 2 + 1][1],
                        smem_u32(Bs + st * B_ST + (b_row0 + nt2 * 16) * STRIDE
                                 + ks * 16 + b_koff));
#pragma unroll
            for (int mt = 0; mt < 4; mt++)
#pragma unroll
                for (int nt = 0; nt < 8; nt++)
                    mma16816(c[mt][nt], a[mt], b[nt]);
        }
        __syncthreads();
    }

    // ------------------------------- epilogue -------------------------------
    int gid = lane >> 2;
    int qid = lane & 3;

    if (EPI == 1) {
        // proj: bias + scatter + residual -> x2 (fp32); fused LN2 -> h2 (bf16)
        float2* red = (float2*)dsm;   // [128][4] per-warp_n partial stats
        size_t dstb[4][2];
#pragma unroll
        for (int mt = 0; mt < 4; mt++) {
#pragma unroll
            for (int h = 0; h < 2; h++) {
                int row = m0 + warp_m * 64 + mt * 16 + gid + h * 8;
                size_t d = scatter_dst(row);
                dstb[mt][h] = d;
                float s = 0.f, ssum = 0.f;
#pragma unroll
                for (int nt = 0; nt < 8; nt++) {
                    int col = warp_n * 64 + nt * 8 + qid * 2;
                    float v0 = c[mt][nt][h * 2 + 0] + bias[col]     + extra[d + col];
                    float v1 = c[mt][nt][h * 2 + 1] + bias[col + 1] + extra[d + col + 1];
                    c[mt][nt][h * 2 + 0] = v0;
                    c[mt][nt][h * 2 + 1] = v1;
                    *(float2*)(out + d + col) = make_float2(v0, v1);
                    s += v0 + v1;
                    ssum += v0 * v0 + v1 * v1;
                }
                // reduce over qid lanes (lane bits 0,1)
#pragma unroll
                for (int o = 1; o <= 2; o <<= 1) {
                    s    += __shfl_xor_sync(0xffffffffu, s,    o);
                    ssum += __shfl_xor_sync(0xffffffffu, ssum, o);
                }
                if (qid == 0) {
                    int crow = warp_m * 64 + mt * 16 + gid + h * 8;
                    red[crow * 4 + warp_n] = make_float2(s, ssum);
                }
            }
        }
        __syncthreads();
#pragma unroll
        for (int mt = 0; mt < 4; mt++) {
#pragma unroll
            for (int h = 0; h < 2; h++) {
                int crow = warp_m * 64 + mt * 16 + gid + h * 8;
                float S = 0.f, SS = 0.f;
#pragma unroll
                for (int wn = 0; wn < 4; wn++) {
                    float2 p = red[crow * 4 + wn];
                    S += p.x; SS += p.y;
                }
                float mu   = S * (1.f / DIM);
                float var  = SS * (1.f / DIM) - mu * mu;
                float rstd = rsqrtf(var + 1e-5f);
                size_t d = dstb[mt][h];
#pragma unroll
                for (int nt = 0; nt < 8; nt++) {
                    int col = warp_n * 64 + nt * 8 + qid * 2;
                    float h0 = (c[mt][nt][h * 2 + 0] - mu) * rstd * w2[col]     + b2[col];
                    float h1 = (c[mt][nt][h * 2 + 1] - mu) * rstd * w2[col + 1] + b2[col + 1];
                    *(uint32_t*)(outb + d + col) = packbf(h0, h1);
                }
            }
        }
        return;
    }

#pragma unroll
    for (int mt = 0; mt < 4; mt++) {
        int r0 = m0 + warp_m * 64 + mt * 16 + gid;
        int r1 = r0 + 8;
        size_t base0 = (size_t)r0 * Ntot;
        size_t base1 = (size_t)r1 * Ntot;
#pragma unroll
        for (int nt = 0; nt < 8; nt++) {
            int col = n0 + warp_n * 64 + nt * 8 + qid * 2;
            float b0 = bias[col], b1 = bias[col + 1];
            float v00 = c[mt][nt][0] + b0, v01 = c[mt][nt][1] + b1;
            float v10 = c[mt][nt][2] + b0, v11 = c[mt][nt][3] + b1;
            if (EPI == 0) {
                *(uint32_t*)(outb + base0 + col) = packbf(v00, v01);
                *(uint32_t*)(outb + base1 + col) = packbf(v10, v11);
            } else if (EPI == 2) {
                const float isq2 = 0.70710678118654752f;
                float g00 = 0.5f * v00 * (1.f + erff(v00 * isq2));
                float g01 = 0.5f * v01 * (1.f + erff(v01 * isq2));
                float g10 = 0.5f * v10 * (1.f + erff(v10 * isq2));
                float g11 = 0.5f * v11 * (1.f + erff(v11 * isq2));
                *(uint32_t*)(outb + base0 + col) = packbf(g00, g01);
                *(uint32_t*)(outb + base1 + col) = packbf(g10, g11);
            } else {
                *(float2*)(out + base0 + col) =
                    make_float2(v00 + extra[base0 + col], v01 + extra[base0 + col + 1]);
                *(float2*)(out + base1 + col) =
                    make_float2(v10 + extra[base1 + col], v11 + extra[base1 + col + 1]);
            }
        }
    }
}

// ---------------------------------------------------------------------------
// Windowed attention via mma.sync. One block per (window, head), 128 thr.
// ---------------------------------------------------------------------------
__global__ void __launch_bounds__(128)
attn_mma(const bf16* __restrict__ qkv, const float* __restrict__ rpb,
         const int* __restrict__ relidx, const float* __restrict__ mask,
         bf16* __restrict__ out)
{
    __shared__ bf16 qs[64][STRIDE];
    __shared__ bf16 ks[64][STRIDE];
    __shared__ bf16 vs[64][STRIDE];
    __shared__ float rpb_s[169];

    int blk  = blockIdx.x;
    int head = blk & 7;
    int win  = blk >> 3;
    int tid  = threadIdx.x;
    int lane = tid & 31;
    int warp = tid >> 5;

    for (int i = tid; i < 300; i += 128) {
        ((uint32_t*)qs)[980 + i] = 0;
        ((uint32_t*)ks)[980 + i] = 0;
        ((uint32_t*)vs)[980 + i] = 0;
    }
    const bf16* base = qkv + (size_t)win * NTOK * QKVDIM + head * HEAD_DIM;
    for (int idx = tid; idx < NTOK * 4; idx += 128) {
        int t  = idx >> 2;
        int ch = (idx & 3) << 3;
        const bf16* p = base + (size_t)t * QKVDIM + ch;
        *(uint4*)&qs[t][ch] = *(const uint4*)(p);
        *(uint4*)&ks[t][ch] = *(const uint4*)(p + 256);
        *(uint4*)&vs[t][ch] = *(const uint4*)(p + 512);
    }
    for (int i = tid; i < 169; i += 128) rpb_s[i] = rpb[i * HEADS + head];
    __syncthreads();

    int wm  = warp * 16;
    int gid = lane >> 2;
    int qid = lane & 3;

    uint32_t aq[2][4];
#pragma unroll
    for (int kt = 0; kt < 2; kt++)
        ldsm_x4(aq[kt][0], aq[kt][1], aq[kt][2], aq[kt][3],
                smem_u32(&qs[wm + (lane & 15)][kt * 16 + ((lane >> 4) << 3)]));

    uint32_t bk[2][8][2];
#pragma unroll
    for (int kt = 0; kt < 2; kt++)
#pragma unroll
        for (int nt2 = 0; nt2 < 4; nt2++)
            ldsm_x4(bk[kt][nt2 * 2][0], bk[kt][nt2 * 2][1],
                    bk[kt][nt2 * 2 + 1][0], bk[kt][nt2 * 2 + 1][1],
                    smem_u32(&ks[nt2 * 16 + (lane & 7) + ((lane >> 4) << 3)]
                                [kt * 16 + (((lane >> 3) & 1) << 3)]));

    float c[8][4];
#pragma unroll
    for (int nt = 0; nt < 8; nt++)
#pragma unroll
        for (int e = 0; e < 4; e++) c[nt][e] = 0.f;
#pragma unroll
    for (int kt = 0; kt < 2; kt++)
#pragma unroll
        for (int nt = 0; nt < 8; nt++)
            mma16816(c[nt], aq[kt], bk[kt][nt]);

    const float scale = 0.17677669529663687f;
    const float* mrow = mask + (size_t)(win & 63) * (NTOK * NTOK);
#pragma unroll
    for (int nt = 0; nt < 8; nt++) {
        int j0 = nt * 8 + qid * 2;
#pragma unroll
        for (int e = 0; e < 4; e++) {
            int i = wm + gid + ((e >> 1) << 3);
            int j = j0 + (e & 1);
            if (j < NTOK && i < NTOK) {
                int ij = i * NTOK + j;
                c[nt][e] = c[nt][e] * scale + rpb_s[relidx[ij]] + mrow[ij];
            } else {
                c[nt][e] = -1e30f;
            }
        }
    }

    float mx0 = -1e30f, mx1 = -1e30f;
#pragma unroll
    for (int nt = 0; nt < 8; nt++) {
        mx0 = fmaxf(mx0, fmaxf(c[nt][0], c[nt][1]));
        mx1 = fmaxf(mx1, fmaxf(c[nt][2], c[nt][3]));
    }
#pragma unroll
    for (int o = 1; o <= 2; o <<= 1) {
        mx0 = fmaxf(mx0, __shfl_xor_sync(0xffffffffu, mx0, o));
        mx1 = fmaxf(mx1, __shfl_xor_sync(0xffffffffu, mx1, o));
    }
    float s0 = 0.f, s1 = 0.f;
#pragma unroll
    for (int nt = 0; nt < 8; nt++) {
        c[nt][0] = __expf(c[nt][0] - mx0); s0 += c[nt][0];
        c[nt][1] = __expf(c[nt][1] - mx0); s0 += c[nt][1];
        c[nt][2] = __expf(c[nt][2] - mx1); s1 += c[nt][2];
        c[nt][3] = __expf(c[nt][3] - mx1); s1 += c[nt][3];
    }
#pragma unroll
    for (int o = 1; o <= 2; o <<= 1) {
        s0 += __shfl_xor_sync(0xffffffffu, s0, o);
        s1 += __shfl_xor_sync(0xffffffffu, s1, o);
    }
    float inv0 = 1.f / s0, inv1 = 1.f / s1;
#pragma unroll
    for (int nt = 0; nt < 8; nt++) {
        c[nt][0] *= inv0; c[nt][1] *= inv0;
        c[nt][2] *= inv1; c[nt][3] *= inv1;
    }

    uint32_t ap[4][4];
#pragma unroll
    for (int kt = 0; kt < 4; kt++) {
        ap[kt][0] = packbf(c[2 * kt][0],     c[2 * kt][1]);
        ap[kt][1] = packbf(c[2 * kt][2],     c[2 * kt][3]);
        ap[kt][2] = packbf(c[2 * kt + 1][0], c[2 * kt + 1][1]);
        ap[kt][3] = packbf(c[2 * kt + 1][2], c[2 * kt + 1][3]);
    }

    float o[4][4];
#pragma unroll
    for (int nt = 0; nt < 4; nt++)
#pragma unroll
        for (int e = 0; e < 4; e++) o[nt][e] = 0.f;
#pragma unroll
    for (int kt = 0; kt < 4; kt++) {
#pragma unroll
        for (int ng = 0; ng < 2; ng++) {
            uint32_t r0, r1, r2, r3;
            ldsm_x4t(r0, r1, r2, r3,
                smem_u32(&vs[kt * 16 + (lane & 7) + (((lane >> 3) & 1) << 3)]
                            [ng * 16 + ((lane >> 4) << 3)]));
            uint32_t bv0[2] = {r0, r1};
            uint32_t bv1[2] = {r2, r3};
            mma16816(o[ng * 2],     ap[kt], bv0);
            mma16816(o[ng * 2 + 1], ap[kt], bv1);
        }
    }

    int i0 = wm + gid;
    int i1 = i0 + 8;
    size_t ob0 = ((size_t)win * NTOK + i0) * DIM + head * HEAD_DIM;
    size_t ob1 = ((size_t)win * NTOK + i1) * DIM + head * HEAD_DIM;
#pragma unroll
    for (int nt = 0; nt < 4; nt++) {
        int n = nt * 8 + qid * 2;
        if (i0 < NTOK) *(uint32_t*)(out + ob0 + n) = packbf(o[nt][0], o[nt][1]);
        if (i1 < NTOK) *(uint32_t*)(out + ob1 + n) = packbf(o[nt][2], o[nt][3]);
    }
}

// ---------------------------------------------------------------------------
extern "C" void kernel_launch(void* const* d_in, const int* in_sizes, int n_in,
                              void* d_out, int out_size)
{
    const float* x     = (const float*)d_in[0];
    const float* n1w   = (const float*)d_in[1];
    const float* n1b   = (const float*)d_in[2];
    const float* qkvw  = (const float*)d_in[3];
    const float* qkvb  = (const float*)d_in[4];
    const float* rpb   = (const float*)d_in[5];
    const float* projw = (const float*)d_in[6];
    const float* projb = (const float*)d_in[7];
    const float* n2w   = (const float*)d_in[8];
    const float* n2b   = (const float*)d_in[9];
    const float* fc1w  = (const float*)d_in[10];
    const float* fc1b  = (const float*)d_in[11];
    const float* fc2w  = (const float*)d_in[12];
    const float* fc2b  = (const float*)d_in[13];
    const int*   ridx  = (const int*)d_in[14];
    const float* amask = (const float*)d_in[15];
    float* outp = (float*)d_out;

    bf16 *hwin, *qkvb16, *attnb, *h2b, *hbufb, *wqkv, *wproj, *wfc1, *wfc2;
    float *x2;
    cudaGetSymbolAddress((void**)&hwin,   g_hwin_b);
    cudaGetSymbolAddress((void**)&qkvb16, g_qkv_b);
    cudaGetSymbolAddress((void**)&attnb,  g_attn_b);
    cudaGetSymbolAddress((void**)&x2,     g_x2);
    cudaGetSymbolAddress((void**)&h2b,    g_h2_b);
    cudaGetSymbolAddress((void**)&hbufb,  g_hbuf_b);
    cudaGetSymbolAddress((void**)&wqkv,   g_wqkv_b);
    cudaGetSymbolAddress((void**)&wproj,  g_wproj_b);
    cudaGetSymbolAddress((void**)&wfc1,   g_wfc1_b);
    cudaGetSymbolAddress((void**)&wfc2,   g_wfc2_b);

    static bool attr_done = false;
    if (!attr_done) {
        cudaFuncSetAttribute(gemm256<0>, cudaFuncAttributeMaxDynamicSharedMemorySize, SMEM_BYTES);
        cudaFuncSetAttribute(gemm256<1>, cudaFuncAttributeMaxDynamicSharedMemorySize, SMEM_BYTES);
        cudaFuncSetAttribute(gemm256<2>, cudaFuncAttributeMaxDynamicSharedMemorySize, SMEM_BYTES);
        cudaFuncSetAttribute(gemm256<3>, cudaFuncAttributeMaxDynamicSharedMemorySize, SMEM_BYTES);
        attr_done = true;
    }

    // weight conversion
    cvt_kernel<<<(QKVDIM * DIM + 255) / 256, 256>>>(qkvw,  wqkv,  QKVDIM * DIM);
    cvt_kernel<<<(DIM * DIM + 255) / 256, 256>>>(projw, wproj, DIM * DIM);
    cvt_kernel<<<(HIDDEN * DIM + 255) / 256, 256>>>(fc1w,  wfc1,  HIDDEN * DIM);
    cvt_kernel<<<(DIM * HIDDEN + 255) / 256, 256>>>(fc2w,  wfc2,  DIM * HIDDEN);

    // 1. LN1 + shift + window partition -> bf16
    ln_kernel<<<TOK / 8, 256>>>(x, n1w, n1b, hwin);
    // 2. QKV GEMM [TOK,256] x [768,256]^T -> bf16
    gemm256<0><<<dim3(QKVDIM / 256, TOK / 128), 256, SMEM_BYTES>>>(
        hwin, wqkv, qkvb, nullptr, nullptr, nullptr, nullptr, qkvb16, DIM, QKVDIM);
    // 3. windowed attention (mma.sync) -> bf16
    attn_mma<<<2048 * HEADS, 128>>>(qkvb16, rpb, ridx, amask, attnb);
    // 4. proj GEMM + scatter + residual -> x2 ; fused LN2 -> h2b
    gemm256<1><<<dim3(1, TOK / 128), 256, SMEM_BYTES>>>(
        attnb, wproj, projb, x, n2w, n2b, x2, h2b, DIM, DIM);
    // 5. FC1 + GELU -> bf16
    gemm256<2><<<dim3(HIDDEN / 256, TOK / 128), 256, SMEM_BYTES>>>(
        h2b, wfc1, fc1b, nullptr, nullptr, nullptr, nullptr, hbufb, DIM, HIDDEN);
    // 6. FC2 + bias + residual -> final fp32
    gemm256<3><<<dim3(1, TOK / 128), 256, SMEM_BYTES>>>(
        hbufb, wfc2, fc2b, x2, nullptr, nullptr, outp, nullptr, HIDDEN, DIM);
}

// round 12
// speedup vs baseline: 1.0616x; 1.0616x over previous
#include <cuda_runtime.h>
#include <cuda_bf16.h>
#include <math.h>
#include <stdint.h>

// ---------------------------------------------------------------------------
// Swin block: GEMMs + attention via mma.sync bf16 (fp32 accum).
// R9 tile shape (BN=128, 64x32/warp) for qkv/fc1/fc2; dedicated 64x256 proj
// kernel with fused LN2. Single fused weight-convert kernel.
// ---------------------------------------------------------------------------

#define TOK      100352
#define DIM      256
#define HIDDEN   1024
#define QKVDIM   768
#define HEADS    8
#define HEAD_DIM 32
#define NTOK     49
#define HW       3136
#define SHIFT    3

typedef __nv_bfloat16 bf16;

// ------------------------- scratch (device globals) ------------------------
__device__ __align__(16) bf16  g_hwin_b[(size_t)TOK * DIM];
__device__ __align__(16) bf16  g_qkv_b [(size_t)TOK * QKVDIM];
__device__ __align__(16) bf16  g_attn_b[(size_t)TOK * DIM];
__device__ __align__(16) float g_x2    [(size_t)TOK * DIM];
__device__ __align__(16) bf16  g_h2_b  [(size_t)TOK * DIM];
__device__ __align__(16) bf16  g_hbuf_b[(size_t)TOK * HIDDEN];
__device__ __align__(16) bf16  g_wqkv_b [QKVDIM * DIM];
__device__ __align__(16) bf16  g_wproj_b[DIM * DIM];
__device__ __align__(16) bf16  g_wfc1_b [HIDDEN * DIM];
__device__ __align__(16) bf16  g_wfc2_b [DIM * HIDDEN];

// ------------------------------ PTX helpers --------------------------------
__device__ __forceinline__ uint32_t smem_u32(const void* p) {
    uint32_t a;
    asm("{ .reg .u64 t; cvta.to.shared.u64 t, %1; cvt.u32.u64 %0, t; }"
        : "=r"(a) : "l"(p));
    return a;
}
__device__ __forceinline__ void cp_async16(uint32_t dst, const void* src) {
    asm volatile("cp.async.cg.shared.global [%0], [%1], 16;"
                 :: "r"(dst), "l"(src));
}
#define CP_COMMIT() asm volatile("cp.async.commit_group;")
#define CP_WAIT(n)  asm volatile("cp.async.wait_group %0;" :: "n"(n))

__device__ __forceinline__ void ldsm_x4(uint32_t& r0, uint32_t& r1,
                                        uint32_t& r2, uint32_t& r3, uint32_t a) {
    asm volatile("ldmatrix.sync.aligned.m8n8.x4.shared.b16 {%0,%1,%2,%3}, [%4];"
                 : "=r"(r0), "=r"(r1), "=r"(r2), "=r"(r3) : "r"(a));
}
__device__ __forceinline__ void ldsm_x4t(uint32_t& r0, uint32_t& r1,
                                         uint32_t& r2, uint32_t& r3, uint32_t a) {
    asm volatile("ldmatrix.sync.aligned.m8n8.x4.trans.shared.b16 {%0,%1,%2,%3}, [%4];"
                 : "=r"(r0), "=r"(r1), "=r"(r2), "=r"(r3) : "r"(a));
}
__device__ __forceinline__ void mma16816(float* d, const uint32_t* a,
                                         const uint32_t* b) {
    asm volatile(
        "mma.sync.aligned.m16n8k16.row.col.f32.bf16.bf16.f32 "
        "{%0,%1,%2,%3}, {%4,%5,%6,%7}, {%8,%9}, {%0,%1,%2,%3};"
        : "+f"(d[0]), "+f"(d[1]), "+f"(d[2]), "+f"(d[3])
        : "r"(a[0]), "r"(a[1]), "r"(a[2]), "r"(a[3]), "r"(b[0]), "r"(b[1]));
}
__device__ __forceinline__ uint32_t packbf(float lo, float hi) {
    uint32_t r;
    asm("cvt.rn.bf16x2.f32 %0, %1, %2;" : "=r"(r) : "f"(hi), "f"(lo));
    return r;
}
__device__ __forceinline__ size_t scatter_dst(int row) {
    int bz = row / HW;
    int r  = row - bz * HW;
    int wI = r / NTOK;
    int t2 = r - wI * NTOK;
    int wh = wI >> 3, ww = wI & 7;
    int ii = t2 / 7,  jj = t2 - (t2 / 7) * 7;
    int sh = (wh * 7 + ii + SHIFT) % 56;
    int sw = (ww * 7 + jj + SHIFT) % 56;
    return ((size_t)bz * HW + sh * 56 + sw) * DIM;
}

// ---------------------------------------------------------------------------
// LN1 -> bf16, gather with cyclic shift + window partition.
// ---------------------------------------------------------------------------
__global__ void ln_kernel(const float* __restrict__ in,
                          const float* __restrict__ w,
                          const float* __restrict__ b,
                          bf16* __restrict__ out)
{
    int warp = threadIdx.x >> 5;
    int lane = threadIdx.x & 31;
    int row  = blockIdx.x * 8 + warp;

    int bz = row / HW;
    int r  = row - bz * HW;
    int wI = r / NTOK;
    int t2 = r - wI * NTOK;
    int wh = wI >> 3, ww = wI & 7;
    int i  = t2 / 7,  j  = t2 - (t2 / 7) * 7;
    int sh = (wh * 7 + i + SHIFT) % 56;
    int sw = (ww * 7 + j + SHIFT) % 56;
    const float* src = in + ((size_t)bz * HW + sh * 56 + sw) * DIM;

    float v[8];
    float s = 0.f, ss = 0.f;
#pragma unroll
    for (int k = 0; k < 8; k++) {
        v[k] = src[lane + 32 * k];
        s  += v[k];
        ss += v[k] * v[k];
    }
#pragma unroll
    for (int o = 16; o; o >>= 1) {
        s  += __shfl_xor_sync(0xffffffffu, s,  o);
        ss += __shfl_xor_sync(0xffffffffu, ss, o);
    }
    float mu   = s * (1.f / DIM);
    float var  = ss * (1.f / DIM) - mu * mu;
    float rstd = rsqrtf(var + 1e-5f);

    bf16* dst = out + (size_t)row * DIM;
#pragma unroll
    for (int k = 0; k < 8; k++) {
        int c = lane + 32 * k;
        dst[c] = __float2bfloat16((v[k] - mu) * rstd * w[c] + b[c]);
    }
}

// ---------------------------------------------------------------------------
// One fused weight convert (4 tensors, 786432 elems total).
// ---------------------------------------------------------------------------
#define N_QKVW (QKVDIM * DIM)                    // 196608
#define N_PROJW (DIM * DIM)                      // 65536
#define N_FC1W (HIDDEN * DIM)                    // 262144
#define N_FC2W (DIM * HIDDEN)                    // 262144
#define N_CVT (N_QKVW + N_PROJW + N_FC1W + N_FC2W)

__global__ void cvt4_kernel(const float* __restrict__ s0, bf16* __restrict__ d0,
                            const float* __restrict__ s1, bf16* __restrict__ d1,
                            const float* __restrict__ s2, bf16* __restrict__ d2,
                            const float* __restrict__ s3, bf16* __restrict__ d3)
{
    int i = blockIdx.x * 256 + threadIdx.x;
    if (i < N_QKVW) {
        d0[i] = __float2bfloat16(s0[i]);
    } else if (i < N_QKVW + N_PROJW) {
        int j = i - N_QKVW;
        d1[j] = __float2bfloat16(s1[j]);
    } else if (i < N_QKVW + N_PROJW + N_FC1W) {
        int j = i - N_QKVW - N_PROJW;
        d2[j] = __float2bfloat16(s2[j]);
    } else if (i < N_CVT) {
        int j = i - N_QKVW - N_PROJW - N_FC1W;
        d3[j] = __float2bfloat16(s3[j]);
    }
}

// ---------------------------------------------------------------------------
// bf16 mma.sync GEMM (R9 shape): BM=BN=128, BK=32, 256 thr, 64x32/warp.
// EPI: 0 qkv(+bias -> bf16)  2 fc1(+bias, gelu -> bf16)  3 fc2(+bias+residual)
// ---------------------------------------------------------------------------
#define STRIDE 40

template <int EPI>
__global__ void __launch_bounds__(256)
gemm_mma(const bf16* __restrict__ A, const bf16* __restrict__ W,
         const float* __restrict__ bias, const float* __restrict__ extra,
         float* __restrict__ out, bf16* __restrict__ outb,
         int K, int Ntot)
{
    __shared__ bf16 As[2][128][STRIDE];
    __shared__ bf16 Bs[2][128][STRIDE];

    int tid    = threadIdx.x;
    int lane   = tid & 31;
    int wid    = tid >> 5;
    int warp_m = wid & 1;
    int warp_n = wid >> 1;
    int m0     = blockIdx.y * 128;
    int n0     = blockIdx.x * 128;

    int lr = tid >> 2;
    int lc = (tid & 3) << 3;

    float c[4][4][4];
#pragma unroll
    for (int i = 0; i < 4; i++)
#pragma unroll
        for (int j = 0; j < 4; j++)
#pragma unroll
            for (int k = 0; k < 4; k++) c[i][j][k] = 0.f;

    int nk = K >> 5;

    {
#pragma unroll
        for (int t = 0; t < 2; t++) {
            int r = lr + t * 64;
            cp_async16(smem_u32(&As[0][r][lc]), A + (size_t)(m0 + r) * K + lc);
            cp_async16(smem_u32(&Bs[0][r][lc]), W + (size_t)(n0 + r) * K + lc);
        }
        CP_COMMIT();
    }

    int a_row  = warp_m * 64 + (lane & 15);
    int a_koff = (lane >> 4) << 3;
    int b_row0 = warp_n * 32 + (lane & 7) + ((lane >> 4) << 3);
    int b_koff = ((lane >> 3) & 1) << 3;

    for (int kk = 0; kk < nk; kk++) {
        int st = kk & 1;
        if (kk + 1 < nk) {
            int kb = (kk + 1) << 5;
#pragma unroll
            for (int t = 0; t < 2; t++) {
                int r = lr + t * 64;
                cp_async16(smem_u32(&As[st ^ 1][r][lc]),
                           A + (size_t)(m0 + r) * K + kb + lc);
                cp_async16(smem_u32(&Bs[st ^ 1][r][lc]),
                           W + (size_t)(n0 + r) * K + kb + lc);
            }
            CP_COMMIT();
            CP_WAIT(1);
        } else {
            CP_WAIT(0);
        }
        __syncthreads();

#pragma unroll
        for (int ks = 0; ks < 2; ks++) {
            uint32_t a[4][4];
            uint32_t b[4][2];
#pragma unroll
            for (int mt = 0; mt < 4; mt++)
                ldsm_x4(a[mt][0], a[mt][1], a[mt][2], a[mt][3],
                        smem_u32(&As[st][a_row + mt * 16][ks * 16 + a_koff]));
#pragma unroll
            for (int np = 0; np < 2; np++)
                ldsm_x4(b[np * 2][0], b[np * 2][1], b[np * 2 + 1][0], b[np * 2 + 1][1],
                        smem_u32(&Bs[st][b_row0 + np * 16][ks * 16 + b_koff]));
#pragma unroll
            for (int mt = 0; mt < 4; mt++)
#pragma unroll
                for (int nt = 0; nt < 4; nt++)
                    mma16816(c[mt][nt], a[mt], b[nt]);
        }
        __syncthreads();
    }

    int gid = lane >> 2;
    int qid = lane & 3;

#pragma unroll
    for (int mt = 0; mt < 4; mt++) {
        int r0 = m0 + warp_m * 64 + mt * 16 + gid;
        int r1 = r0 + 8;
        size_t base0 = (size_t)r0 * Ntot;
        size_t base1 = (size_t)r1 * Ntot;
#pragma unroll
        for (int nt = 0; nt < 4; nt++) {
            int col = n0 + warp_n * 32 + nt * 8 + qid * 2;
            float b0 = bias[col], b1 = bias[col + 1];
            float v00 = c[mt][nt][0] + b0, v01 = c[mt][nt][1] + b1;
            float v10 = c[mt][nt][2] + b0, v11 = c[mt][nt][3] + b1;
            if (EPI == 0) {
                *(uint32_t*)(outb + base0 + col) = packbf(v00, v01);
                *(uint32_t*)(outb + base1 + col) = packbf(v10, v11);
            } else if (EPI == 2) {
                const float isq2 = 0.70710678118654752f;
                float g00 = 0.5f * v00 * (1.f + erff(v00 * isq2));
                float g01 = 0.5f * v01 * (1.f + erff(v01 * isq2));
                float g10 = 0.5f * v10 * (1.f + erff(v10 * isq2));
                float g11 = 0.5f * v11 * (1.f + erff(v11 * isq2));
                *(uint32_t*)(outb + base0 + col) = packbf(g00, g01);
                *(uint32_t*)(outb + base1 + col) = packbf(g10, g11);
            } else {
                *(float2*)(out + base0 + col) =
                    make_float2(v00 + extra[base0 + col], v01 + extra[base0 + col + 1]);
                *(float2*)(out + base1 + col) =
                    make_float2(v10 + extra[base1 + col], v11 + extra[base1 + col + 1]);
            }
        }
    }
}

// ---------------------------------------------------------------------------
// proj GEMM with fused LN2. BM=64, BN=256 (full rows per CTA), BK=32,
// 256 thr = 8 warps, warp tile 64x32 (warp_n = wid). Dynamic smem.
// epilogue: v = c + bias + x[scattered]; write x2 (fp32); LN2(v) -> h2 (bf16).
// ---------------------------------------------------------------------------
#define PA_ST (64 * STRIDE)
#define PB_ST (256 * STRIDE)
#define PROJ_SMEM ((2 * PA_ST + 2 * PB_ST) * 2)   // 51200 bytes

__global__ void __launch_bounds__(256)
gemm_proj_ln(const bf16* __restrict__ A, const bf16* __restrict__ W,
             const float* __restrict__ bias, const float* __restrict__ x,
             const float* __restrict__ w2, const float* __restrict__ b2,
             float* __restrict__ x2, bf16* __restrict__ h2)
{
    extern __shared__ char dsm[];
    bf16* As = (bf16*)dsm;
    bf16* Bs = (bf16*)dsm + 2 * PA_ST;

    int tid  = threadIdx.x;
    int lane = tid & 31;
    int wid  = tid >> 5;       // warp_n: 8 x 32 cols
    int m0   = blockIdx.x * 64;

    int lr = tid >> 2;         // 0..63
    int lc = (tid & 3) << 3;

    float c[4][4][4];
#pragma unroll
    for (int i = 0; i < 4; i++)
#pragma unroll
        for (int j = 0; j < 4; j++)
#pragma unroll
            for (int k = 0; k < 4; k++) c[i][j][k] = 0.f;

    // prologue stage 0  (K = DIM = 256, nk = 8)
    {
        cp_async16(smem_u32(As + lr * STRIDE + lc), A + (size_t)(m0 + lr) * DIM + lc);
#pragma unroll
        for (int t = 0; t < 4; t++) {
            int r = lr + t * 64;
            cp_async16(smem_u32(Bs + r * STRIDE + lc), W + (size_t)r * DIM + lc);
        }
        CP_COMMIT();
    }

    int a_row  = lane & 15;
    int a_koff = (lane >> 4) << 3;
    int b_row0 = wid * 32 + (lane & 7) + ((lane >> 4) << 3);
    int b_koff = ((lane >> 3) & 1) << 3;

    for (int kk = 0; kk < 8; kk++) {
        int st = kk & 1;
        if (kk + 1 < 8) {
            int kb = (kk + 1) << 5;
            int s2 = st ^ 1;
            cp_async16(smem_u32(As + s2 * PA_ST + lr * STRIDE + lc),
                       A + (size_t)(m0 + lr) * DIM + kb + lc);
#pragma unroll
            for (int t = 0; t < 4; t++) {
                int r = lr + t * 64;
                cp_async16(smem_u32(Bs + s2 * PB_ST + r * STRIDE + lc),
                           W + (size_t)r * DIM + kb + lc);
            }
            CP_COMMIT();
            CP_WAIT(1);
        } else {
            CP_WAIT(0);
        }
        __syncthreads();

#pragma unroll
        for (int ks = 0; ks < 2; ks++) {
            uint32_t a[4][4];
            uint32_t b[4][2];
#pragma unroll
            for (int mt = 0; mt < 4; mt++)
                ldsm_x4(a[mt][0], a[mt][1], a[mt][2], a[mt][3],
                        smem_u32(As + st * PA_ST + (a_row + mt * 16) * STRIDE
                                 + ks * 16 + a_koff));
#pragma unroll
            for (int np = 0; np < 2; np++)
                ldsm_x4(b[np * 2][0], b[np * 2][1], b[np * 2 + 1][0], b[np * 2 + 1][1],
                        smem_u32(Bs + st * PB_ST + (b_row0 + np * 16) * STRIDE
                                 + ks * 16 + b_koff));
#pragma unroll
            for (int mt = 0; mt < 4; mt++)
#pragma unroll
                for (int nt = 0; nt < 4; nt++)
                    mma16816(c[mt][nt], a[mt], b[nt]);
        }
        __syncthreads();
    }

    // ---- epilogue: bias + scatter + residual -> x2; fused LN2 -> h2 -------
    int gid = lane >> 2;
    int qid = lane & 3;
    float2* red = (float2*)dsm;   // [64][8], mainloop smem is dead

    size_t dstb[4][2];
#pragma unroll
    for (int mt = 0; mt < 4; mt++) {
#pragma unroll
        for (int h = 0; h < 2; h++) {
            int rl  = mt * 16 + gid + h * 8;      // 0..63
            size_t d = scatter_dst(m0 + rl);
            dstb[mt][h] = d;
            float s = 0.f, ssum = 0.f;
#pragma unroll
            for (int nt = 0; nt < 4; nt++) {
                int col = wid * 32 + nt * 8 + qid * 2;
                float v0 = c[mt][nt][h * 2 + 0] + bias[col]     + x[d + col];
                float v1 = c[mt][nt][h * 2 + 1] + bias[col + 1] + x[d + col + 1];
                c[mt][nt][h * 2 + 0] = v0;
                c[mt][nt][h * 2 + 1] = v1;
                *(float2*)(x2 + d + col) = make_float2(v0, v1);
                s    += v0 + v1;
                ssum += v0 * v0 + v1 * v1;
            }
#pragma unroll
            for (int o = 1; o <= 2; o <<= 1) {
                s    += __shfl_xor_sync(0xffffffffu, s,    o);
                ssum += __shfl_xor_sync(0xffffffffu, ssum, o);
            }
            if (qid == 0) red[rl * 8 + wid] = make_float2(s, ssum);
        }
    }
    __syncthreads();

#pragma unroll
    for (int mt = 0; mt < 4; mt++) {
#pragma unroll
        for (int h = 0; h < 2; h++) {
            int rl = mt * 16 + gid + h * 8;
            float S = 0.f, SS = 0.f;
#pragma unroll
            for (int wn = 0; wn < 8; wn++) {
                float2 p = red[rl * 8 + wn];
                S += p.x; SS += p.y;
            }
            float mu   = S * (1.f / DIM);
            float var  = SS * (1.f / DIM) - mu * mu;
            float rstd = rsqrtf(var + 1e-5f);
            size_t d = dstb[mt][h];
#pragma unroll
            for (int nt = 0; nt < 4; nt++) {
                int col = wid * 32 + nt * 8 + qid * 2;
                float h0 = (c[mt][nt][h * 2 + 0] - mu) * rstd * w2[col]     + b2[col];
                float h1 = (c[mt][nt][h * 2 + 1] - mu) * rstd * w2[col + 1] + b2[col + 1];
                *(uint32_t*)(h2 + d + col) = packbf(h0, h1);
            }
        }
    }
}

// ---------------------------------------------------------------------------
// Windowed attention via mma.sync. One block per (window, head), 128 thr.
// ---------------------------------------------------------------------------
__global__ void __launch_bounds__(128)
attn_mma(const bf16* __restrict__ qkv, const float* __restrict__ rpb,
         const int* __restrict__ relidx, const float* __restrict__ mask,
         bf16* __restrict__ out)
{
    __shared__ bf16 qs[64][STRIDE];
    __shared__ bf16 ks[64][STRIDE];
    __shared__ bf16 vs[64][STRIDE];
    __shared__ float rpb_s[169];

    int blk  = blockIdx.x;
    int head = blk & 7;
    int win  = blk >> 3;
    int tid  = threadIdx.x;
    int lane = tid & 31;
    int warp = tid >> 5;

    for (int i = tid; i < 300; i += 128) {
        ((uint32_t*)qs)[980 + i] = 0;
        ((uint32_t*)ks)[980 + i] = 0;
        ((uint32_t*)vs)[980 + i] = 0;
    }
    const bf16* base = qkv + (size_t)win * NTOK * QKVDIM + head * HEAD_DIM;
    for (int idx = tid; idx < NTOK * 4; idx += 128) {
        int t  = idx >> 2;
        int ch = (idx & 3) << 3;
        const bf16* p = base + (size_t)t * QKVDIM + ch;
        *(uint4*)&qs[t][ch] = *(const uint4*)(p);
        *(uint4*)&ks[t][ch] = *(const uint4*)(p + 256);
        *(uint4*)&vs[t][ch] = *(const uint4*)(p + 512);
    }
    for (int i = tid; i < 169; i += 128) rpb_s[i] = rpb[i * HEADS + head];
    __syncthreads();

    int wm  = warp * 16;
    int gid = lane >> 2;
    int qid = lane & 3;

    uint32_t aq[2][4];
#pragma unroll
    for (int kt = 0; kt < 2; kt++)
        ldsm_x4(aq[kt][0], aq[kt][1], aq[kt][2], aq[kt][3],
                smem_u32(&qs[wm + (lane & 15)][kt * 16 + ((lane >> 4) << 3)]));

    uint32_t bk[2][8][2];
#pragma unroll
    for (int kt = 0; kt < 2; kt++)
#pragma unroll
        for (int nt2 = 0; nt2 < 4; nt2++)
            ldsm_x4(bk[kt][nt2 * 2][0], bk[kt][nt2 * 2][1],
                    bk[kt][nt2 * 2 + 1][0], bk[kt][nt2 * 2 + 1][1],
                    smem_u32(&ks[nt2 * 16 + (lane & 7) + ((lane >> 4) << 3)]
                                [kt * 16 + (((lane >> 3) & 1) << 3)]));

    float c[8][4];
#pragma unroll
    for (int nt = 0; nt < 8; nt++)
#pragma unroll
        for (int e = 0; e < 4; e++) c[nt][e] = 0.f;
#pragma unroll
    for (int kt = 0; kt < 2; kt++)
#pragma unroll
        for (int nt = 0; nt < 8; nt++)
            mma16816(c[nt], aq[kt], bk[kt][nt]);

    const float scale = 0.17677669529663687f;
    const float* mrow = mask + (size_t)(win & 63) * (NTOK * NTOK);
#pragma unroll
    for (int nt = 0; nt < 8; nt++) {
        int j0 = nt * 8 + qid * 2;
#pragma unroll
        for (int e = 0; e < 4; e++) {
            int i = wm + gid + ((e >> 1) << 3);
            int j = j0 + (e & 1);
            if (j < NTOK && i < NTOK) {
                int ij = i * NTOK + j;
                c[nt][e] = c[nt][e] * scale + rpb_s[relidx[ij]] + mrow[ij];
            } else {
                c[nt][e] = -1e30f;
            }
        }
    }

    float mx0 = -1e30f, mx1 = -1e30f;
#pragma unroll
    for (int nt = 0; nt < 8; nt++) {
        mx0 = fmaxf(mx0, fmaxf(c[nt][0], c[nt][1]));
        mx1 = fmaxf(mx1, fmaxf(c[nt][2], c[nt][3]));
    }
#pragma unroll
    for (int o = 1; o <= 2; o <<= 1) {
        mx0 = fmaxf(mx0, __shfl_xor_sync(0xffffffffu, mx0, o));
        mx1 = fmaxf(mx1, __shfl_xor_sync(0xffffffffu, mx1, o));
    }
    float s0 = 0.f, s1 = 0.f;
#pragma unroll
    for (int nt = 0; nt < 8; nt++) {
        c[nt][0] = __expf(c[nt][0] - mx0); s0 += c[nt][0];
        c[nt][1] = __expf(c[nt][1] - mx0); s0 += c[nt][1];
        c[nt][2] = __expf(c[nt][2] - mx1); s1 += c[nt][2];
        c[nt][3] = __expf(c[nt][3] - mx1); s1 += c[nt][3];
    }
#pragma unroll
    for (int o = 1; o <= 2; o <<= 1) {
        s0 += __shfl_xor_sync(0xffffffffu, s0, o);
        s1 += __shfl_xor_sync(0xffffffffu, s1, o);
    }
    float inv0 = 1.f / s0, inv1 = 1.f / s1;
#pragma unroll
    for (int nt = 0; nt < 8; nt++) {
        c[nt][0] *= inv0; c[nt][1] *= inv0;
        c[nt][2] *= inv1; c[nt][3] *= inv1;
    }

    uint32_t ap[4][4];
#pragma unroll
    for (int kt = 0; kt < 4; kt++) {
        ap[kt][0] = packbf(c[2 * kt][0],     c[2 * kt][1]);
        ap[kt][1] = packbf(c[2 * kt][2],     c[2 * kt][3]);
        ap[kt][2] = packbf(c[2 * kt + 1][0], c[2 * kt + 1][1]);
        ap[kt][3] = packbf(c[2 * kt + 1][2], c[2 * kt + 1][3]);
    }

    float o[4][4];
#pragma unroll
    for (int nt = 0; nt < 4; nt++)
#pragma unroll
        for (int e = 0; e < 4; e++) o[nt][e] = 0.f;
#pragma unroll
    for (int kt = 0; kt < 4; kt++) {
#pragma unroll
        for (int ng = 0; ng < 2; ng++) {
            uint32_t r0, r1, r2, r3;
            ldsm_x4t(r0, r1, r2, r3,
                smem_u32(&vs[kt * 16 + (lane & 7) + (((lane >> 3) & 1) << 3)]
                            [ng * 16 + ((lane >> 4) << 3)]));
            uint32_t bv0[2] = {r0, r1};
            uint32_t bv1[2] = {r2, r3};
            mma16816(o[ng * 2],     ap[kt], bv0);
            mma16816(o[ng * 2 + 1], ap[kt], bv1);
        }
    }

    int i0 = wm + gid;
    int i1 = i0 + 8;
    size_t ob0 = ((size_t)win * NTOK + i0) * DIM + head * HEAD_DIM;
    size_t ob1 = ((size_t)win * NTOK + i1) * DIM + head * HEAD_DIM;
#pragma unroll
    for (int nt = 0; nt < 4; nt++) {
        int n = nt * 8 + qid * 2;
        if (i0 < NTOK) *(uint32_t*)(out + ob0 + n) = packbf(o[nt][0], o[nt][1]);
        if (i1 < NTOK) *(uint32_t*)(out + ob1 + n) = packbf(o[nt][2], o[nt][3]);
    }
}

// ---------------------------------------------------------------------------
extern "C" void kernel_launch(void* const* d_in, const int* in_sizes, int n_in,
                              void* d_out, int out_size)
{
    const float* x     = (const float*)d_in[0];
    const float* n1w   = (const float*)d_in[1];
    const float* n1b   = (const float*)d_in[2];
    const float* qkvw  = (const float*)d_in[3];
    const float* qkvb  = (const float*)d_in[4];
    const float* rpb   = (const float*)d_in[5];
    const float* projw = (const float*)d_in[6];
    const float* projb = (const float*)d_in[7];
    const float* n2w   = (const float*)d_in[8];
    const float* n2b   = (const float*)d_in[9];
    const float* fc1w  = (const float*)d_in[10];
    const float* fc1b  = (const float*)d_in[11];
    const float* fc2w  = (const float*)d_in[12];
    const float* fc2b  = (const float*)d_in[13];
    const int*   ridx  = (const int*)d_in[14];
    const float* amask = (const float*)d_in[15];
    float* outp = (float*)d_out;

    bf16 *hwin, *qkvb16, *attnb, *h2b, *hbufb, *wqkv, *wproj, *wfc1, *wfc2;
    float *x2;
    cudaGetSymbolAddress((void**)&hwin,   g_hwin_b);
    cudaGetSymbolAddress((void**)&qkvb16, g_qkv_b);
    cudaGetSymbolAddress((void**)&attnb,  g_attn_b);
    cudaGetSymbolAddress((void**)&x2,     g_x2);
    cudaGetSymbolAddress((void**)&h2b,    g_h2_b);
    cudaGetSymbolAddress((void**)&hbufb,  g_hbuf_b);
    cudaGetSymbolAddress((void**)&wqkv,   g_wqkv_b);
    cudaGetSymbolAddress((void**)&wproj,  g_wproj_b);
    cudaGetSymbolAddress((void**)&wfc1,   g_wfc1_b);
    cudaGetSymbolAddress((void**)&wfc2,   g_wfc2_b);

    static bool attr_done = false;
    if (!attr_done) {
        cudaFuncSetAttribute(gemm_proj_ln,
                             cudaFuncAttributeMaxDynamicSharedMemorySize, PROJ_SMEM);
        attr_done = true;
    }

    // 0. fused weight conversion (1 launch)
    cvt4_kernel<<<(N_CVT + 255) / 256, 256>>>(qkvw, wqkv, projw, wproj,
                                              fc1w, wfc1, fc2w, wfc2);
    // 1. LN1 + shift + window partition -> bf16
    ln_kernel<<<TOK / 8, 256>>>(x, n1w, n1b, hwin);
    // 2. QKV GEMM [TOK,256] x [768,256]^T -> bf16
    gemm_mma<0><<<dim3(QKVDIM / 128, TOK / 128), 256>>>(
        hwin, wqkv, qkvb, nullptr, nullptr, qkvb16, DIM, QKVDIM);
    // 3. windowed attention (mma.sync) -> bf16
    attn_mma<<<2048 * HEADS, 128>>>(qkvb16, rpb, ridx, amask, attnb);
    // 4. proj GEMM + scatter + residual -> x2 ; fused LN2 -> h2b
    gemm_proj_ln<<<TOK / 64, 256, PROJ_SMEM>>>(
        attnb, wproj, projb, x, n2w, n2b, x2, h2b);
    // 5. FC1 + GELU -> bf16
    gemm_mma<2><<<dim3(HIDDEN / 128, TOK / 128), 256>>>(
        h2b, wfc1, fc1b, nullptr, nullptr, hbufb, DIM, HIDDEN);
    // 6. FC2 + bias + residual -> final fp32
    gemm_mma<3><<<dim3(DIM / 128, TOK / 128), 256>>>(
        hbufb, wfc2, fc2b, x2, outp, nullptr, HIDDEN, DIM);
}

// round 13
// speedup vs baseline: 1.1079x; 1.0436x over previous
#include <cuda_runtime.h>
#include <cuda_bf16.h>
#include <math.h>
#include <stdint.h>

// ---------------------------------------------------------------------------
// Swin block: GEMMs + attention via mma.sync bf16 (fp32 accum).
// R9 GEMM shape (BN=128, 64x32/warp). Attention uses a precomputed combined
// (rel-pos-bias + shift-mask) bf16 table, padded 64x64 per (head, winclass).
// ---------------------------------------------------------------------------

#define TOK      100352
#define DIM      256
#define HIDDEN   1024
#define QKVDIM   768
#define HEADS    8
#define HEAD_DIM 32
#define NTOK     49
#define HW       3136
#define SHIFT    3

typedef __nv_bfloat16 bf16;

// ------------------------- scratch (device globals) ------------------------
__device__ __align__(16) bf16  g_hwin_b[(size_t)TOK * DIM];
__device__ __align__(16) bf16  g_qkv_b [(size_t)TOK * QKVDIM];
__device__ __align__(16) bf16  g_attn_b[(size_t)TOK * DIM];
__device__ __align__(16) float g_x2    [(size_t)TOK * DIM];
__device__ __align__(16) bf16  g_h2_b  [(size_t)TOK * DIM];
__device__ __align__(16) bf16  g_hbuf_b[(size_t)TOK * HIDDEN];
__device__ __align__(16) bf16  g_wqkv_b [QKVDIM * DIM];
__device__ __align__(16) bf16  g_wproj_b[DIM * DIM];
__device__ __align__(16) bf16  g_wfc1_b [HIDDEN * DIM];
__device__ __align__(16) bf16  g_wfc2_b [DIM * HIDDEN];
__device__ __align__(16) bf16  g_btab  [HEADS * 64 * 64 * 64];   // 4 MB

// ------------------------------ PTX helpers --------------------------------
__device__ __forceinline__ uint32_t smem_u32(const void* p) {
    uint32_t a;
    asm("{ .reg .u64 t; cvta.to.shared.u64 t, %1; cvt.u32.u64 %0, t; }"
        : "=r"(a) : "l"(p));
    return a;
}
__device__ __forceinline__ void cp_async16(uint32_t dst, const void* src) {
    asm volatile("cp.async.cg.shared.global [%0], [%1], 16;"
                 :: "r"(dst), "l"(src));
}
#define CP_COMMIT() asm volatile("cp.async.commit_group;")
#define CP_WAIT(n)  asm volatile("cp.async.wait_group %0;" :: "n"(n))

__device__ __forceinline__ void ldsm_x4(uint32_t& r0, uint32_t& r1,
                                        uint32_t& r2, uint32_t& r3, uint32_t a) {
    asm volatile("ldmatrix.sync.aligned.m8n8.x4.shared.b16 {%0,%1,%2,%3}, [%4];"
                 : "=r"(r0), "=r"(r1), "=r"(r2), "=r"(r3) : "r"(a));
}
__device__ __forceinline__ void ldsm_x4t(uint32_t& r0, uint32_t& r1,
                                         uint32_t& r2, uint32_t& r3, uint32_t a) {
    asm volatile("ldmatrix.sync.aligned.m8n8.x4.trans.shared.b16 {%0,%1,%2,%3}, [%4];"
                 : "=r"(r0), "=r"(r1), "=r"(r2), "=r"(r3) : "r"(a));
}
__device__ __forceinline__ void mma16816(float* d, const uint32_t* a,
                                         const uint32_t* b) {
    asm volatile(
        "mma.sync.aligned.m16n8k16.row.col.f32.bf16.bf16.f32 "
        "{%0,%1,%2,%3}, {%4,%5,%6,%7}, {%8,%9}, {%0,%1,%2,%3};"
        : "+f"(d[0]), "+f"(d[1]), "+f"(d[2]), "+f"(d[3])
        : "r"(a[0]), "r"(a[1]), "r"(a[2]), "r"(a[3]), "r"(b[0]), "r"(b[1]));
}
__device__ __forceinline__ uint32_t packbf(float lo, float hi) {
    uint32_t r;
    asm("cvt.rn.bf16x2.f32 %0, %1, %2;" : "=r"(r) : "f"(hi), "f"(lo));
    return r;
}
__device__ __forceinline__ size_t scatter_dst(int row) {
    int bz = row / HW;
    int r  = row - bz * HW;
    int wI = r / NTOK;
    int t2 = r - wI * NTOK;
    int wh = wI >> 3, ww = wI & 7;
    int ii = t2 / 7,  jj = t2 - (t2 / 7) * 7;
    int sh = (wh * 7 + ii + SHIFT) % 56;
    int sw = (ww * 7 + jj + SHIFT) % 56;
    return ((size_t)bz * HW + sh * 56 + sw) * DIM;
}

// ---------------------------------------------------------------------------
// LayerNorm -> bf16. REMAP: gather with cyclic shift + window partition.
// ---------------------------------------------------------------------------
template <bool REMAP>
__global__ void ln_kernel(const float* __restrict__ in,
                          const float* __restrict__ w,
                          const float* __restrict__ b,
                          bf16* __restrict__ out)
{
    int warp = threadIdx.x >> 5;
    int lane = threadIdx.x & 31;
    int row  = blockIdx.x * 8 + warp;

    const float* src;
    if (REMAP) {
        int bz = row / HW;
        int r  = row - bz * HW;
        int wI = r / NTOK;
        int t2 = r - wI * NTOK;
        int wh = wI >> 3, ww = wI & 7;
        int i  = t2 / 7,  j  = t2 - (t2 / 7) * 7;
        int sh = (wh * 7 + i + SHIFT) % 56;
        int sw = (ww * 7 + j + SHIFT) % 56;
        src = in + ((size_t)bz * HW + sh * 56 + sw) * DIM;
    } else {
        src = in + (size_t)row * DIM;
    }

    float v[8];
    float s = 0.f, ss = 0.f;
#pragma unroll
    for (int k = 0; k < 8; k++) {
        v[k] = src[lane + 32 * k];
        s  += v[k];
        ss += v[k] * v[k];
    }
#pragma unroll
    for (int o = 16; o; o >>= 1) {
        s  += __shfl_xor_sync(0xffffffffu, s,  o);
        ss += __shfl_xor_sync(0xffffffffu, ss, o);
    }
    float mu   = s * (1.f / DIM);
    float var  = ss * (1.f / DIM) - mu * mu;
    float rstd = rsqrtf(var + 1e-5f);

    bf16* dst = out + (size_t)row * DIM;
#pragma unroll
    for (int k = 0; k < 8; k++) {
        int c = lane + 32 * k;
        dst[c] = __float2bfloat16((v[k] - mu) * rstd * w[c] + b[c]);
    }
}

// ---------------------------------------------------------------------------
// Fused weight convert (4 tensors).
// ---------------------------------------------------------------------------
#define N_QKVW (QKVDIM * DIM)
#define N_PROJW (DIM * DIM)
#define N_FC1W (HIDDEN * DIM)
#define N_FC2W (DIM * HIDDEN)
#define N_CVT (N_QKVW + N_PROJW + N_FC1W + N_FC2W)

__global__ void cvt4_kernel(const float* __restrict__ s0, bf16* __restrict__ d0,
                            const float* __restrict__ s1, bf16* __restrict__ d1,
                            const float* __restrict__ s2, bf16* __restrict__ d2,
                            const float* __restrict__ s3, bf16* __restrict__ d3)
{
    int i = blockIdx.x * 256 + threadIdx.x;
    if (i < N_QKVW) {
        d0[i] = __float2bfloat16(s0[i]);
    } else if (i < N_QKVW + N_PROJW) {
        int j = i - N_QKVW;
        d1[j] = __float2bfloat16(s1[j]);
    } else if (i < N_QKVW + N_PROJW + N_FC1W) {
        int j = i - N_QKVW - N_PROJW;
        d2[j] = __float2bfloat16(s2[j]);
    } else if (i < N_CVT) {
        int j = i - N_QKVW - N_PROJW - N_FC1W;
        d3[j] = __float2bfloat16(s3[j]);
    }
}

// ---------------------------------------------------------------------------
// Combined attention bias table: btab[head][wc][i][j] (64x64 padded, bf16)
// = rpb[relidx[i,j], head] + mask[wc, i, j]   (i,j < 49), else -1e30.
// One block per (head, wc), 256 threads, 16 elems each.
// ---------------------------------------------------------------------------
__global__ void bias_prep(const float* __restrict__ rpb,
                          const int* __restrict__ relidx,
                          const float* __restrict__ mask,
                          bf16* __restrict__ btab)
{
    int head = blockIdx.x >> 6;
    int wc   = blockIdx.x & 63;
    bf16* dst = btab + ((size_t)blockIdx.x << 12);
    for (int idx = threadIdx.x; idx < 4096; idx += 256) {
        int i = idx >> 6, j = idx & 63;
        float v = -1e30f;
        if (i < NTOK && j < NTOK) {
            int ij = i * NTOK + j;
            v = rpb[relidx[ij] * HEADS + head] + mask[wc * (NTOK * NTOK) + ij];
        }
        dst[idx] = __float2bfloat16(v);
    }
}

// ---------------------------------------------------------------------------
// bf16 mma.sync GEMM (R9 shape): BM=BN=128, BK=32, 256 thr, 64x32/warp.
// EPI: 0 qkv(+bias->bf16) 1 proj(+bias,scatter+residual->fp32)
//      2 fc1(+bias,gelu->bf16) 3 fc2(+bias+residual->fp32)
// ---------------------------------------------------------------------------
#define STRIDE 40

template <int EPI>
__global__ void __launch_bounds__(256)
gemm_mma(const bf16* __restrict__ A, const bf16* __restrict__ W,
         const float* __restrict__ bias, const float* __restrict__ extra,
         float* __restrict__ out, bf16* __restrict__ outb,
         int K, int Ntot)
{
    __shared__ bf16 As[2][128][STRIDE];
    __shared__ bf16 Bs[2][128][STRIDE];

    int tid    = threadIdx.x;
    int lane   = tid & 31;
    int wid    = tid >> 5;
    int warp_m = wid & 1;
    int warp_n = wid >> 1;
    int m0     = blockIdx.y * 128;
    int n0     = blockIdx.x * 128;

    int lr = tid >> 2;
    int lc = (tid & 3) << 3;

    float c[4][4][4];
#pragma unroll
    for (int i = 0; i < 4; i++)
#pragma unroll
        for (int j = 0; j < 4; j++)
#pragma unroll
            for (int k = 0; k < 4; k++) c[i][j][k] = 0.f;

    int nk = K >> 5;

    {
#pragma unroll
        for (int t = 0; t < 2; t++) {
            int r = lr + t * 64;
            cp_async16(smem_u32(&As[0][r][lc]), A + (size_t)(m0 + r) * K + lc);
            cp_async16(smem_u32(&Bs[0][r][lc]), W + (size_t)(n0 + r) * K + lc);
        }
        CP_COMMIT();
    }

    int a_row  = warp_m * 64 + (lane & 15);
    int a_koff = (lane >> 4) << 3;
    int b_row0 = warp_n * 32 + (lane & 7) + ((lane >> 4) << 3);
    int b_koff = ((lane >> 3) & 1) << 3;

    for (int kk = 0; kk < nk; kk++) {
        int st = kk & 1;
        if (kk + 1 < nk) {
            int kb = (kk + 1) << 5;
#pragma unroll
            for (int t = 0; t < 2; t++) {
                int r = lr + t * 64;
                cp_async16(smem_u32(&As[st ^ 1][r][lc]),
                           A + (size_t)(m0 + r) * K + kb + lc);
                cp_async16(smem_u32(&Bs[st ^ 1][r][lc]),
                           W + (size_t)(n0 + r) * K + kb + lc);
            }
            CP_COMMIT();
            CP_WAIT(1);
        } else {
            CP_WAIT(0);
        }
        __syncthreads();

#pragma unroll
        for (int ks = 0; ks < 2; ks++) {
            uint32_t a[4][4];
            uint32_t b[4][2];
#pragma unroll
            for (int mt = 0; mt < 4; mt++)
                ldsm_x4(a[mt][0], a[mt][1], a[mt][2], a[mt][3],
                        smem_u32(&As[st][a_row + mt * 16][ks * 16 + a_koff]));
#pragma unroll
            for (int np = 0; np < 2; np++)
                ldsm_x4(b[np * 2][0], b[np * 2][1], b[np * 2 + 1][0], b[np * 2 + 1][1],
                        smem_u32(&Bs[st][b_row0 + np * 16][ks * 16 + b_koff]));
#pragma unroll
            for (int mt = 0; mt < 4; mt++)
#pragma unroll
                for (int nt = 0; nt < 4; nt++)
                    mma16816(c[mt][nt], a[mt], b[nt]);
        }
        __syncthreads();
    }

    int gid = lane >> 2;
    int qid = lane & 3;

#pragma unroll
    for (int mt = 0; mt < 4; mt++) {
        int r0 = m0 + warp_m * 64 + mt * 16 + gid;
        int r1 = r0 + 8;
        size_t base0, base1;
        if (EPI == 1) {
            base0 = scatter_dst(r0);
            base1 = scatter_dst(r1);
        } else {
            base0 = (size_t)r0 * Ntot;
            base1 = (size_t)r1 * Ntot;
        }
#pragma unroll
        for (int nt = 0; nt < 4; nt++) {
            int col = n0 + warp_n * 32 + nt * 8 + qid * 2;
            float b0 = bias[col], b1 = bias[col + 1];
            float v00 = c[mt][nt][0] + b0, v01 = c[mt][nt][1] + b1;
            float v10 = c[mt][nt][2] + b0, v11 = c[mt][nt][3] + b1;
            if (EPI == 0) {
                *(uint32_t*)(outb + base0 + col) = packbf(v00, v01);
                *(uint32_t*)(outb + base1 + col) = packbf(v10, v11);
            } else if (EPI == 1) {
                out[base0 + col]     = v00 + extra[base0 + col];
                out[base0 + col + 1] = v01 + extra[base0 + col + 1];
                out[base1 + col]     = v10 + extra[base1 + col];
                out[base1 + col + 1] = v11 + extra[base1 + col + 1];
            } else if (EPI == 2) {
                const float isq2 = 0.70710678118654752f;
                float g00 = 0.5f * v00 * (1.f + erff(v00 * isq2));
                float g01 = 0.5f * v01 * (1.f + erff(v01 * isq2));
                float g10 = 0.5f * v10 * (1.f + erff(v10 * isq2));
                float g11 = 0.5f * v11 * (1.f + erff(v11 * isq2));
                *(uint32_t*)(outb + base0 + col) = packbf(g00, g01);
                *(uint32_t*)(outb + base1 + col) = packbf(g10, g11);
            } else {
                *(float2*)(out + base0 + col) =
                    make_float2(v00 + extra[base0 + col], v01 + extra[base0 + col + 1]);
                *(float2*)(out + base1 + col) =
                    make_float2(v10 + extra[base1 + col], v11 + extra[base1 + col + 1]);
            }
        }
    }
}

// ---------------------------------------------------------------------------
// Windowed attention via mma.sync with precomputed combined bias table.
// One block per (window, head), 128 thr.
// ---------------------------------------------------------------------------
__global__ void __launch_bounds__(128)
attn_mma(const bf16* __restrict__ qkv, const bf16* __restrict__ btab,
         bf16* __restrict__ out)
{
    __shared__ bf16 qs[64][STRIDE];
    __shared__ bf16 ks[64][STRIDE];
    __shared__ bf16 vs[64][STRIDE];

    int blk  = blockIdx.x;
    int head = blk & 7;
    int win  = blk >> 3;
    int tid  = threadIdx.x;
    int lane = tid & 31;
    int warp = tid >> 5;

    for (int i = tid; i < 300; i += 128) {
        ((uint32_t*)qs)[980 + i] = 0;
        ((uint32_t*)ks)[980 + i] = 0;
        ((uint32_t*)vs)[980 + i] = 0;
    }
    const bf16* base = qkv + (size_t)win * NTOK * QKVDIM + head * HEAD_DIM;
    for (int idx = tid; idx < NTOK * 4; idx += 128) {
        int t  = idx >> 2;
        int ch = (idx & 3) << 3;
        const bf16* p = base + (size_t)t * QKVDIM + ch;
        *(uint4*)&qs[t][ch] = *(const uint4*)(p);
        *(uint4*)&ks[t][ch] = *(const uint4*)(p + 256);
        *(uint4*)&vs[t][ch] = *(const uint4*)(p + 512);
    }
    __syncthreads();

    int wm  = warp * 16;
    int gid = lane >> 2;
    int qid = lane & 3;

    uint32_t aq[2][4];
#pragma unroll
    for (int kt = 0; kt < 2; kt++)
        ldsm_x4(aq[kt][0], aq[kt][1], aq[kt][2], aq[kt][3],
                smem_u32(&qs[wm + (lane & 15)][kt * 16 + ((lane >> 4) << 3)]));

    uint32_t bk[2][8][2];
#pragma unroll
    for (int kt = 0; kt < 2; kt++)
#pragma unroll
        for (int nt2 = 0; nt2 < 4; nt2++)
            ldsm_x4(bk[kt][nt2 * 2][0], bk[kt][nt2 * 2][1],
                    bk[kt][nt2 * 2 + 1][0], bk[kt][nt2 * 2 + 1][1],
                    smem_u32(&ks[nt2 * 16 + (lane & 7) + ((lane >> 4) << 3)]
                                [kt * 16 + (((lane >> 3) & 1) << 3)]));

    float c[8][4];
#pragma unroll
    for (int nt = 0; nt < 8; nt++)
#pragma unroll
        for (int e = 0; e < 4; e++) c[nt][e] = 0.f;
#pragma unroll
    for (int kt = 0; kt < 2; kt++)
#pragma unroll
        for (int nt = 0; nt < 8; nt++)
            mma16816(c[nt], aq[kt], bk[kt][nt]);

    // ---- scale + combined bias (bf16 table, padded 64x64) -----------------
    const float scale = 0.17677669529663687f;
    const bf16* bt = btab + (((size_t)((head << 6) | (win & 63))) << 12);
    {
        int i0 = wm + gid;
#pragma unroll
        for (int nt = 0; nt < 8; nt++) {
            int j0 = nt * 8 + qid * 2;
            uint32_t u0 = *(const uint32_t*)(bt + (i0 << 6) + j0);
            uint32_t u1 = *(const uint32_t*)(bt + ((i0 + 8) << 6) + j0);
            c[nt][0] = fmaf(c[nt][0], scale, __uint_as_float(u0 << 16));
            c[nt][1] = fmaf(c[nt][1], scale, __uint_as_float(u0 & 0xffff0000u));
            c[nt][2] = fmaf(c[nt][2], scale, __uint_as_float(u1 << 16));
            c[nt][3] = fmaf(c[nt][3], scale, __uint_as_float(u1 & 0xffff0000u));
        }
    }

    // ---- softmax (rows live in 4 lanes: qid) ------------------------------
    float mx0 = -1e30f, mx1 = -1e30f;
#pragma unroll
    for (int nt = 0; nt < 8; nt++) {
        mx0 = fmaxf(mx0, fmaxf(c[nt][0], c[nt][1]));
        mx1 = fmaxf(mx1, fmaxf(c[nt][2], c[nt][3]));
    }
#pragma unroll
    for (int o = 1; o <= 2; o <<= 1) {
        mx0 = fmaxf(mx0, __shfl_xor_sync(0xffffffffu, mx0, o));
        mx1 = fmaxf(mx1, __shfl_xor_sync(0xffffffffu, mx1, o));
    }
    float s0 = 0.f, s1 = 0.f;
#pragma unroll
    for (int nt = 0; nt < 8; nt++) {
        c[nt][0] = __expf(c[nt][0] - mx0); s0 += c[nt][0];
        c[nt][1] = __expf(c[nt][1] - mx0); s0 += c[nt][1];
        c[nt][2] = __expf(c[nt][2] - mx1); s1 += c[nt][2];
        c[nt][3] = __expf(c[nt][3] - mx1); s1 += c[nt][3];
    }
#pragma unroll
    for (int o = 1; o <= 2; o <<= 1) {
        s0 += __shfl_xor_sync(0xffffffffu, s0, o);
        s1 += __shfl_xor_sync(0xffffffffu, s1, o);
    }
    float inv0 = 1.f / s0, inv1 = 1.f / s1;
#pragma unroll
    for (int nt = 0; nt < 8; nt++) {
        c[nt][0] *= inv0; c[nt][1] *= inv0;
        c[nt][2] *= inv1; c[nt][3] *= inv1;
    }

    uint32_t ap[4][4];
#pragma unroll
    for (int kt = 0; kt < 4; kt++) {
        ap[kt][0] = packbf(c[2 * kt][0],     c[2 * kt][1]);
        ap[kt][1] = packbf(c[2 * kt][2],     c[2 * kt][3]);
        ap[kt][2] = packbf(c[2 * kt + 1][0], c[2 * kt + 1][1]);
        ap[kt][3] = packbf(c[2 * kt + 1][2], c[2 * kt + 1][3]);
    }

    float o[4][4];
#pragma unroll
    for (int nt = 0; nt < 4; nt++)
#pragma unroll
        for (int e = 0; e < 4; e++) o[nt][e] = 0.f;
#pragma unroll
    for (int kt = 0; kt < 4; kt++) {
#pragma unroll
        for (int ng = 0; ng < 2; ng++) {
            uint32_t r0, r1, r2, r3;
            ldsm_x4t(r0, r1, r2, r3,
                smem_u32(&vs[kt * 16 + (lane & 7) + (((lane >> 3) & 1) << 3)]
                            [ng * 16 + ((lane >> 4) << 3)]));
            uint32_t bv0[2] = {r0, r1};
            uint32_t bv1[2] = {r2, r3};
            mma16816(o[ng * 2],     ap[kt], bv0);
            mma16816(o[ng * 2 + 1], ap[kt], bv1);
        }
    }

    int i0 = wm + gid;
    int i1 = i0 + 8;
    size_t ob0 = ((size_t)win * NTOK + i0) * DIM + head * HEAD_DIM;
    size_t ob1 = ((size_t)win * NTOK + i1) * DIM + head * HEAD_DIM;
#pragma unroll
    for (int nt = 0; nt < 4; nt++) {
        int n = nt * 8 + qid * 2;
        if (i0 < NTOK) *(uint32_t*)(out + ob0 + n) = packbf(o[nt][0], o[nt][1]);
        if (i1 < NTOK) *(uint32_t*)(out + ob1 + n) = packbf(o[nt][2], o[nt][3]);
    }
}

// ---------------------------------------------------------------------------
extern "C" void kernel_launch(void* const* d_in, const int* in_sizes, int n_in,
                              void* d_out, int out_size)
{
    const float* x     = (const float*)d_in[0];
    const float* n1w   = (const float*)d_in[1];
    const float* n1b   = (const float*)d_in[2];
    const float* qkvw  = (const float*)d_in[3];
    const float* qkvb  = (const float*)d_in[4];
    const float* rpb   = (const float*)d_in[5];
    const float* projw = (const float*)d_in[6];
    const float* projb = (const float*)d_in[7];
    const float* n2w   = (const float*)d_in[8];
    const float* n2b   = (const float*)d_in[9];
    const float* fc1w  = (const float*)d_in[10];
    const float* fc1b  = (const float*)d_in[11];
    const float* fc2w  = (const float*)d_in[12];
    const float* fc2b  = (const float*)d_in[13];
    const int*   ridx  = (const int*)d_in[14];
    const float* amask = (const float*)d_in[15];
    float* outp = (float*)d_out;

    bf16 *hwin, *qkvb16, *attnb, *h2b, *hbufb, *wqkv, *wproj, *wfc1, *wfc2, *btab;
    float *x2;
    cudaGetSymbolAddress((void**)&hwin,   g_hwin_b);
    cudaGetSymbolAddress((void**)&qkvb16, g_qkv_b);
    cudaGetSymbolAddress((void**)&attnb,  g_attn_b);
    cudaGetSymbolAddress((void**)&x2,     g_x2);
    cudaGetSymbolAddress((void**)&h2b,    g_h2_b);
    cudaGetSymbolAddress((void**)&hbufb,  g_hbuf_b);
    cudaGetSymbolAddress((void**)&wqkv,   g_wqkv_b);
    cudaGetSymbolAddress((void**)&wproj,  g_wproj_b);
    cudaGetSymbolAddress((void**)&wfc1,   g_wfc1_b);
    cudaGetSymbolAddress((void**)&wfc2,   g_wfc2_b);
    cudaGetSymbolAddress((void**)&btab,   g_btab);

    // 0a. fused weight conversion
    cvt4_kernel<<<(N_CVT + 255) / 256, 256>>>(qkvw, wqkv, projw, wproj,
                                              fc1w, wfc1, fc2w, wfc2);
    // 0b. combined attention bias table (8 heads x 64 window classes)
    bias_prep<<<HEADS * 64, 256>>>(rpb, ridx, amask, btab);
    // 1. LN1 + shift + window partition -> bf16
    ln_kernel<true><<<TOK / 8, 256>>>(x, n1w, n1b, hwin);
    // 2. QKV GEMM [TOK,256] x [768,256]^T -> bf16
    gemm_mma<0><<<dim3(QKVDIM / 128, TOK / 128), 256>>>(
        hwin, wqkv, qkvb, nullptr, nullptr, qkvb16, DIM, QKVDIM);
    // 3. windowed attention -> bf16
    attn_mma<<<2048 * HEADS, 128>>>(qkvb16, btab, attnb);
    // 4. proj GEMM + scatter + residual -> x2 (fp32)
    gemm_mma<1><<<dim3(DIM / 128, TOK / 128), 256>>>(
        attnb, wproj, projb, x, x2, nullptr, DIM, DIM);
    // 5. LN2 -> bf16
    ln_kernel<false><<<TOK / 8, 256>>>(x2, n2w, n2b, h2b);
    // 6. FC1 + GELU -> bf16
    gemm_mma<2><<<dim3(HIDDEN / 128, TOK / 128), 256>>>(
        h2b, wfc1, fc1b, nullptr, nullptr, hbufb, DIM, HIDDEN);
    // 7. FC2 + bias + residual -> final fp32
    gemm_mma<3><<<dim3(DIM / 128, TOK / 128), 256>>>(
        hbufb, wfc2, fc2b, x2, outp, nullptr, HIDDEN, DIM);
}

// round 14
// speedup vs baseline: 1.1360x; 1.0254x over previous
#include <cuda_runtime.h>
#include <cuda_bf16.h>
#include <math.h>
#include <stdint.h>

// ---------------------------------------------------------------------------
// Swin block: GEMMs + attention via mma.sync bf16 (fp32 accum).
// GEMMs: BM=BN=128, BK=32, 64x32/warp, 3-stage cp.async (1 barrier/K-iter).
// Attention uses precomputed combined (rpb + shift-mask) bf16 table.
// ---------------------------------------------------------------------------

#define TOK      100352
#define DIM      256
#define HIDDEN   1024
#define QKVDIM   768
#define HEADS    8
#define HEAD_DIM 32
#define NTOK     49
#define HW       3136
#define SHIFT    3

typedef __nv_bfloat16 bf16;

// ------------------------- scratch (device globals) ------------------------
__device__ __align__(16) bf16  g_hwin_b[(size_t)TOK * DIM];
__device__ __align__(16) bf16  g_qkv_b [(size_t)TOK * QKVDIM];
__device__ __align__(16) bf16  g_attn_b[(size_t)TOK * DIM];
__device__ __align__(16) float g_x2    [(size_t)TOK * DIM];
__device__ __align__(16) bf16  g_h2_b  [(size_t)TOK * DIM];
__device__ __align__(16) bf16  g_hbuf_b[(size_t)TOK * HIDDEN];
__device__ __align__(16) bf16  g_wqkv_b [QKVDIM * DIM];
__device__ __align__(16) bf16  g_wproj_b[DIM * DIM];
__device__ __align__(16) bf16  g_wfc1_b [HIDDEN * DIM];
__device__ __align__(16) bf16  g_wfc2_b [DIM * HIDDEN];
__device__ __align__(16) bf16  g_btab  [HEADS * 64 * 64 * 64];   // 4 MB

// ------------------------------ PTX helpers --------------------------------
__device__ __forceinline__ uint32_t smem_u32(const void* p) {
    uint32_t a;
    asm("{ .reg .u64 t; cvta.to.shared.u64 t, %1; cvt.u32.u64 %0, t; }"
        : "=r"(a) : "l"(p));
    return a;
}
__device__ __forceinline__ void cp_async16(uint32_t dst, const void* src) {
    asm volatile("cp.async.cg.shared.global [%0], [%1], 16;"
                 :: "r"(dst), "l"(src));
}
#define CP_COMMIT() asm volatile("cp.async.commit_group;")
#define CP_WAIT(n)  asm volatile("cp.async.wait_group %0;" :: "n"(n))

__device__ __forceinline__ void ldsm_x4(uint32_t& r0, uint32_t& r1,
                                        uint32_t& r2, uint32_t& r3, uint32_t a) {
    asm volatile("ldmatrix.sync.aligned.m8n8.x4.shared.b16 {%0,%1,%2,%3}, [%4];"
                 : "=r"(r0), "=r"(r1), "=r"(r2), "=r"(r3) : "r"(a));
}
__device__ __forceinline__ void ldsm_x4t(uint32_t& r0, uint32_t& r1,
                                         uint32_t& r2, uint32_t& r3, uint32_t a) {
    asm volatile("ldmatrix.sync.aligned.m8n8.x4.trans.shared.b16 {%0,%1,%2,%3}, [%4];"
                 : "=r"(r0), "=r"(r1), "=r"(r2), "=r"(r3) : "r"(a));
}
__device__ __forceinline__ void mma16816(float* d, const uint32_t* a,
                                         const uint32_t* b) {
    asm volatile(
        "mma.sync.aligned.m16n8k16.row.col.f32.bf16.bf16.f32 "
        "{%0,%1,%2,%3}, {%4,%5,%6,%7}, {%8,%9}, {%0,%1,%2,%3};"
        : "+f"(d[0]), "+f"(d[1]), "+f"(d[2]), "+f"(d[3])
        : "r"(a[0]), "r"(a[1]), "r"(a[2]), "r"(a[3]), "r"(b[0]), "r"(b[1]));
}
__device__ __forceinline__ uint32_t packbf(float lo, float hi) {
    uint32_t r;
    asm("cvt.rn.bf16x2.f32 %0, %1, %2;" : "=r"(r) : "f"(hi), "f"(lo));
    return r;
}
__device__ __forceinline__ size_t scatter_dst(int row) {
    int bz = row / HW;
    int r  = row - bz * HW;
    int wI = r / NTOK;
    int t2 = r - wI * NTOK;
    int wh = wI >> 3, ww = wI & 7;
    int ii = t2 / 7,  jj = t2 - (t2 / 7) * 7;
    int sh = (wh * 7 + ii + SHIFT) % 56;
    int sw = (ww * 7 + jj + SHIFT) % 56;
    return ((size_t)bz * HW + sh * 56 + sw) * DIM;
}

// ---------------------------------------------------------------------------
// LayerNorm -> bf16. REMAP: gather with cyclic shift + window partition.
// ---------------------------------------------------------------------------
template <bool REMAP>
__global__ void ln_kernel(const float* __restrict__ in,
                          const float* __restrict__ w,
                          const float* __restrict__ b,
                          bf16* __restrict__ out)
{
    int warp = threadIdx.x >> 5;
    int lane = threadIdx.x & 31;
    int row  = blockIdx.x * 8 + warp;

    const float* src;
    if (REMAP) {
        int bz = row / HW;
        int r  = row - bz * HW;
        int wI = r / NTOK;
        int t2 = r - wI * NTOK;
        int wh = wI >> 3, ww = wI & 7;
        int i  = t2 / 7,  j  = t2 - (t2 / 7) * 7;
        int sh = (wh * 7 + i + SHIFT) % 56;
        int sw = (ww * 7 + j + SHIFT) % 56;
        src = in + ((size_t)bz * HW + sh * 56 + sw) * DIM;
    } else {
        src = in + (size_t)row * DIM;
    }

    float v[8];
    float s = 0.f, ss = 0.f;
#pragma unroll
    for (int k = 0; k < 8; k++) {
        v[k] = src[lane + 32 * k];
        s  += v[k];
        ss += v[k] * v[k];
    }
#pragma unroll
    for (int o = 16; o; o >>= 1) {
        s  += __shfl_xor_sync(0xffffffffu, s,  o);
        ss += __shfl_xor_sync(0xffffffffu, ss, o);
    }
    float mu   = s * (1.f / DIM);
    float var  = ss * (1.f / DIM) - mu * mu;
    float rstd = rsqrtf(var + 1e-5f);

    bf16* dst = out + (size_t)row * DIM;
#pragma unroll
    for (int k = 0; k < 8; k++) {
        int c = lane + 32 * k;
        dst[c] = __float2bfloat16((v[k] - mu) * rstd * w[c] + b[c]);
    }
}

// ---------------------------------------------------------------------------
// Fused weight convert (4 tensors).
// ---------------------------------------------------------------------------
#define N_QKVW (QKVDIM * DIM)
#define N_PROJW (DIM * DIM)
#define N_FC1W (HIDDEN * DIM)
#define N_FC2W (DIM * HIDDEN)
#define N_CVT (N_QKVW + N_PROJW + N_FC1W + N_FC2W)

__global__ void cvt4_kernel(const float* __restrict__ s0, bf16* __restrict__ d0,
                            const float* __restrict__ s1, bf16* __restrict__ d1,
                            const float* __restrict__ s2, bf16* __restrict__ d2,
                            const float* __restrict__ s3, bf16* __restrict__ d3)
{
    int i = blockIdx.x * 256 + threadIdx.x;
    if (i < N_QKVW) {
        d0[i] = __float2bfloat16(s0[i]);
    } else if (i < N_QKVW + N_PROJW) {
        int j = i - N_QKVW;
        d1[j] = __float2bfloat16(s1[j]);
    } else if (i < N_QKVW + N_PROJW + N_FC1W) {
        int j = i - N_QKVW - N_PROJW;
        d2[j] = __float2bfloat16(s2[j]);
    } else if (i < N_CVT) {
        int j = i - N_QKVW - N_PROJW - N_FC1W;
        d3[j] = __float2bfloat16(s3[j]);
    }
}

// ---------------------------------------------------------------------------
// Combined attention bias table: btab[head][wc][i][j] (64x64 padded, bf16).
// ---------------------------------------------------------------------------
__global__ void bias_prep(const float* __restrict__ rpb,
                          const int* __restrict__ relidx,
                          const float* __restrict__ mask,
                          bf16* __restrict__ btab)
{
    int head = blockIdx.x >> 6;
    int wc   = blockIdx.x & 63;
    bf16* dst = btab + ((size_t)blockIdx.x << 12);
    for (int idx = threadIdx.x; idx < 4096; idx += 256) {
        int i = idx >> 6, j = idx & 63;
        float v = -1e30f;
        if (i < NTOK && j < NTOK) {
            int ij = i * NTOK + j;
            v = rpb[relidx[ij] * HEADS + head] + mask[wc * (NTOK * NTOK) + ij];
        }
        dst[idx] = __float2bfloat16(v);
    }
}

// ---------------------------------------------------------------------------
// bf16 mma.sync GEMM: BM=BN=128, BK=32, 256 thr, 64x32/warp, 3-stage cp.async.
// One __syncthreads per K-iter. Dynamic smem (3 stages x (A+B)).
// EPI: 0 qkv(+bias->bf16) 1 proj(+bias,scatter+residual->fp32)
//      2 fc1(+bias,gelu->bf16) 3 fc2(+bias+residual->fp32)
// ---------------------------------------------------------------------------
#define STRIDE 40
#define TILE_E (128 * STRIDE)                    // bf16 elems per tile
#define GEMM_SMEM (3 * 2 * TILE_E * 2)           // 61440 bytes

template <int EPI>
__global__ void __launch_bounds__(256)
gemm_mma(const bf16* __restrict__ A, const bf16* __restrict__ W,
         const float* __restrict__ bias, const float* __restrict__ extra,
         float* __restrict__ out, bf16* __restrict__ outb,
         int K, int Ntot)
{
    extern __shared__ bf16 dsm[];
    bf16* As = dsm;                 // 3 x TILE_E
    bf16* Bs = dsm + 3 * TILE_E;    // 3 x TILE_E

    int tid    = threadIdx.x;
    int lane   = tid & 31;
    int wid    = tid >> 5;
    int warp_m = wid & 1;
    int warp_n = wid >> 1;
    int m0     = blockIdx.y * 128;
    int n0     = blockIdx.x * 128;

    int lr = tid >> 2;
    int lc = (tid & 3) << 3;

    float c[4][4][4];
#pragma unroll
    for (int i = 0; i < 4; i++)
#pragma unroll
        for (int j = 0; j < 4; j++)
#pragma unroll
            for (int k = 0; k < 4; k++) c[i][j][k] = 0.f;

    int nk = K >> 5;

    // prologue: stages 0 and 1 (separate commit groups)
#pragma unroll
    for (int p = 0; p < 2; p++) {
        if (p < nk) {
            int kb = p << 5;
#pragma unroll
            for (int t = 0; t < 2; t++) {
                int r = lr + t * 64;
                cp_async16(smem_u32(As + p * TILE_E + r * STRIDE + lc),
                           A + (size_t)(m0 + r) * K + kb + lc);
                cp_async16(smem_u32(Bs + p * TILE_E + r * STRIDE + lc),
                           W + (size_t)(n0 + r) * K + kb + lc);
            }
        }
        CP_COMMIT();
    }

    int a_row  = warp_m * 64 + (lane & 15);
    int a_koff = (lane >> 4) << 3;
    int b_row0 = warp_n * 32 + (lane & 7) + ((lane >> 4) << 3);
    int b_koff = ((lane >> 3) & 1) << 3;

    int st = 0;      // stage of current compute iter
    int wr = 2;      // stage to fill next
    for (int kk = 0; kk < nk; kk++) {
        if (kk + 1 < nk) CP_WAIT(1); else CP_WAIT(0);
        __syncthreads();

        // prefetch stage kk+2 (safe: all threads are past compute of kk-1)
        if (kk + 2 < nk) {
            int kb = (kk + 2) << 5;
#pragma unroll
            for (int t = 0; t < 2; t++) {
                int r = lr + t * 64;
                cp_async16(smem_u32(As + wr * TILE_E + r * STRIDE + lc),
                           A + (size_t)(m0 + r) * K + kb + lc);
                cp_async16(smem_u32(Bs + wr * TILE_E + r * STRIDE + lc),
                           W + (size_t)(n0 + r) * K + kb + lc);
            }
        }
        CP_COMMIT();

        const bf16* Ast = As + st * TILE_E;
        const bf16* Bst = Bs + st * TILE_E;
#pragma unroll
        for (int ks = 0; ks < 2; ks++) {
            uint32_t a[4][4];
            uint32_t b[4][2];
#pragma unroll
            for (int mt = 0; mt < 4; mt++)
                ldsm_x4(a[mt][0], a[mt][1], a[mt][2], a[mt][3],
                        smem_u32(Ast + (a_row + mt * 16) * STRIDE + ks * 16 + a_koff));
#pragma unroll
            for (int np = 0; np < 2; np++)
                ldsm_x4(b[np * 2][0], b[np * 2][1], b[np * 2 + 1][0], b[np * 2 + 1][1],
                        smem_u32(Bst + (b_row0 + np * 16) * STRIDE + ks * 16 + b_koff));
#pragma unroll
            for (int mt = 0; mt < 4; mt++)
#pragma unroll
                for (int nt = 0; nt < 4; nt++)
                    mma16816(c[mt][nt], a[mt], b[nt]);
        }
        st = (st + 1 == 3) ? 0 : st + 1;
        wr = (wr + 1 == 3) ? 0 : wr + 1;
    }

    int gid = lane >> 2;
    int qid = lane & 3;

#pragma unroll
    for (int mt = 0; mt < 4; mt++) {
        int r0 = m0 + warp_m * 64 + mt * 16 + gid;
        int r1 = r0 + 8;
        size_t base0, base1;
        if (EPI == 1) {
            base0 = scatter_dst(r0);
            base1 = scatter_dst(r1);
        } else {
            base0 = (size_t)r0 * Ntot;
            base1 = (size_t)r1 * Ntot;
        }
#pragma unroll
        for (int nt = 0; nt < 4; nt++) {
            int col = n0 + warp_n * 32 + nt * 8 + qid * 2;
            float b0 = bias[col], b1 = bias[col + 1];
            float v00 = c[mt][nt][0] + b0, v01 = c[mt][nt][1] + b1;
            float v10 = c[mt][nt][2] + b0, v11 = c[mt][nt][3] + b1;
            if (EPI == 0) {
                *(uint32_t*)(outb + base0 + col) = packbf(v00, v01);
                *(uint32_t*)(outb + base1 + col) = packbf(v10, v11);
            } else if (EPI == 1) {
                out[base0 + col]     = v00 + extra[base0 + col];
                out[base0 + col + 1] = v01 + extra[base0 + col + 1];
                out[base1 + col]     = v10 + extra[base1 + col];
                out[base1 + col + 1] = v11 + extra[base1 + col + 1];
            } else if (EPI == 2) {
                const float isq2 = 0.70710678118654752f;
                float g00 = 0.5f * v00 * (1.f + erff(v00 * isq2));
                float g01 = 0.5f * v01 * (1.f + erff(v01 * isq2));
                float g10 = 0.5f * v10 * (1.f + erff(v10 * isq2));
                float g11 = 0.5f * v11 * (1.f + erff(v11 * isq2));
                *(uint32_t*)(outb + base0 + col) = packbf(g00, g01);
                *(uint32_t*)(outb + base1 + col) = packbf(g10, g11);
            } else {
                *(float2*)(out + base0 + col) =
                    make_float2(v00 + extra[base0 + col], v01 + extra[base0 + col + 1]);
                *(float2*)(out + base1 + col) =
                    make_float2(v10 + extra[base1 + col], v11 + extra[base1 + col + 1]);
            }
        }
    }
}

// ---------------------------------------------------------------------------
// Windowed attention via mma.sync with precomputed combined bias table.
// One block per (window, head), 128 thr.
// ---------------------------------------------------------------------------
__global__ void __launch_bounds__(128)
attn_mma(const bf16* __restrict__ qkv, const bf16* __restrict__ btab,
         bf16* __restrict__ out)
{
    __shared__ bf16 qs[64][STRIDE];
    __shared__ bf16 ks[64][STRIDE];
    __shared__ bf16 vs[64][STRIDE];

    int blk  = blockIdx.x;
    int head = blk & 7;
    int win  = blk >> 3;
    int tid  = threadIdx.x;
    int lane = tid & 31;
    int warp = tid >> 5;

    for (int i = tid; i < 300; i += 128) {
        ((uint32_t*)qs)[980 + i] = 0;
        ((uint32_t*)ks)[980 + i] = 0;
        ((uint32_t*)vs)[980 + i] = 0;
    }
    const bf16* base = qkv + (size_t)win * NTOK * QKVDIM + head * HEAD_DIM;
    for (int idx = tid; idx < NTOK * 4; idx += 128) {
        int t  = idx >> 2;
        int ch = (idx & 3) << 3;
        const bf16* p = base + (size_t)t * QKVDIM + ch;
        *(uint4*)&qs[t][ch] = *(const uint4*)(p);
        *(uint4*)&ks[t][ch] = *(const uint4*)(p + 256);
        *(uint4*)&vs[t][ch] = *(const uint4*)(p + 512);
    }
    __syncthreads();

    int wm  = warp * 16;
    int gid = lane >> 2;
    int qid = lane & 3;

    uint32_t aq[2][4];
#pragma unroll
    for (int kt = 0; kt < 2; kt++)
        ldsm_x4(aq[kt][0], aq[kt][1], aq[kt][2], aq[kt][3],
                smem_u32(&qs[wm + (lane & 15)][kt * 16 + ((lane >> 4) << 3)]));

    uint32_t bk[2][8][2];
#pragma unroll
    for (int kt = 0; kt < 2; kt++)
#pragma unroll
        for (int nt2 = 0; nt2 < 4; nt2++)
            ldsm_x4(bk[kt][nt2 * 2][0], bk[kt][nt2 * 2][1],
                    bk[kt][nt2 * 2 + 1][0], bk[kt][nt2 * 2 + 1][1],
                    smem_u32(&ks[nt2 * 16 + (lane & 7) + ((lane >> 4) << 3)]
                                [kt * 16 + (((lane >> 3) & 1) << 3)]));

    float c[8][4];
#pragma unroll
    for (int nt = 0; nt < 8; nt++)
#pragma unroll
        for (int e = 0; e < 4; e++) c[nt][e] = 0.f;
#pragma unroll
    for (int kt = 0; kt < 2; kt++)
#pragma unroll
        for (int nt = 0; nt < 8; nt++)
            mma16816(c[nt], aq[kt], bk[kt][nt]);

    const float scale = 0.17677669529663687f;
    const bf16* bt = btab + (((size_t)((head << 6) | (win & 63))) << 12);
    {
        int i0 = wm + gid;
#pragma unroll
        for (int nt = 0; nt < 8; nt++) {
            int j0 = nt * 8 + qid * 2;
            uint32_t u0 = *(const uint32_t*)(bt + (i0 << 6) + j0);
            uint32_t u1 = *(const uint32_t*)(bt + ((i0 + 8) << 6) + j0);
            c[nt][0] = fmaf(c[nt][0], scale, __uint_as_float(u0 << 16));
            c[nt][1] = fmaf(c[nt][1], scale, __uint_as_float(u0 & 0xffff0000u));
            c[nt][2] = fmaf(c[nt][2], scale, __uint_as_float(u1 << 16));
            c[nt][3] = fmaf(c[nt][3], scale, __uint_as_float(u1 & 0xffff0000u));
        }
    }

    float mx0 = -1e30f, mx1 = -1e30f;
#pragma unroll
    for (int nt = 0; nt < 8; nt++) {
        mx0 = fmaxf(mx0, fmaxf(c[nt][0], c[nt][1]));
        mx1 = fmaxf(mx1, fmaxf(c[nt][2], c[nt][3]));
    }
#pragma unroll
    for (int o = 1; o <= 2; o <<= 1) {
        mx0 = fmaxf(mx0, __shfl_xor_sync(0xffffffffu, mx0, o));
        mx1 = fmaxf(mx1, __shfl_xor_sync(0xffffffffu, mx1, o));
    }
    float s0 = 0.f, s1 = 0.f;
#pragma unroll
    for (int nt = 0; nt < 8; nt++) {
        c[nt][0] = __expf(c[nt][0] - mx0); s0 += c[nt][0];
        c[nt][1] = __expf(c[nt][1] - mx0); s0 += c[nt][1];
        c[nt][2] = __expf(c[nt][2] - mx1); s1 += c[nt][2];
        c[nt][3] = __expf(c[nt][3] - mx1); s1 += c[nt][3];
    }
#pragma unroll
    for (int o = 1; o <= 2; o <<= 1) {
        s0 += __shfl_xor_sync(0xffffffffu, s0, o);
        s1 += __shfl_xor_sync(0xffffffffu, s1, o);
    }
    float inv0 = 1.f / s0, inv1 = 1.f / s1;
#pragma unroll
    for (int nt = 0; nt < 8; nt++) {
        c[nt][0] *= inv0; c[nt][1] *= inv0;
        c[nt][2] *= inv1; c[nt][3] *= inv1;
    }

    uint32_t ap[4][4];
#pragma unroll
    for (int kt = 0; kt < 4; kt++) {
        ap[kt][0] = packbf(c[2 * kt][0],     c[2 * kt][1]);
        ap[kt][1] = packbf(c[2 * kt][2],     c[2 * kt][3]);
        ap[kt][2] = packbf(c[2 * kt + 1][0], c[2 * kt + 1][1]);
        ap[kt][3] = packbf(c[2 * kt + 1][2], c[2 * kt + 1][3]);
    }

    float o[4][4];
#pragma unroll
    for (int nt = 0; nt < 4; nt++)
#pragma unroll
        for (int e = 0; e < 4; e++) o[nt][e] = 0.f;
#pragma unroll
    for (int kt = 0; kt < 4; kt++) {
#pragma unroll
        for (int ng = 0; ng < 2; ng++) {
            uint32_t r0, r1, r2, r3;
            ldsm_x4t(r0, r1, r2, r3,
                smem_u32(&vs[kt * 16 + (lane & 7) + (((lane >> 3) & 1) << 3)]
                            [ng * 16 + ((lane >> 4) << 3)]));
            uint32_t bv0[2] = {r0, r1};
            uint32_t bv1[2] = {r2, r3};
            mma16816(o[ng * 2],     ap[kt], bv0);
            mma16816(o[ng * 2 + 1], ap[kt], bv1);
        }
    }

    int i0 = wm + gid;
    int i1 = i0 + 8;
    size_t ob0 = ((size_t)win * NTOK + i0) * DIM + head * HEAD_DIM;
    size_t ob1 = ((size_t)win * NTOK + i1) * DIM + head * HEAD_DIM;
#pragma unroll
    for (int nt = 0; nt < 4; nt++) {
        int n = nt * 8 + qid * 2;
        if (i0 < NTOK) *(uint32_t*)(out + ob0 + n) = packbf(o[nt][0], o[nt][1]);
        if (i1 < NTOK) *(uint32_t*)(out + ob1 + n) = packbf(o[nt][2], o[nt][3]);
    }
}

// ---------------------------------------------------------------------------
extern "C" void kernel_launch(void* const* d_in, const int* in_sizes, int n_in,
                              void* d_out, int out_size)
{
    const float* x     = (const float*)d_in[0];
    const float* n1w   = (const float*)d_in[1];
    const float* n1b   = (const float*)d_in[2];
    const float* qkvw  = (const float*)d_in[3];
    const float* qkvb  = (const float*)d_in[4];
    const float* rpb   = (const float*)d_in[5];
    const float* projw = (const float*)d_in[6];
    const float* projb = (const float*)d_in[7];
    const float* n2w   = (const float*)d_in[8];
    const float* n2b   = (const float*)d_in[9];
    const float* fc1w  = (const float*)d_in[10];
    const float* fc1b  = (const float*)d_in[11];
    const float* fc2w  = (const float*)d_in[12];
    const float* fc2b  = (const float*)d_in[13];
    const int*   ridx  = (const int*)d_in[14];
    const float* amask = (const float*)d_in[15];
    float* outp = (float*)d_out;

    bf16 *hwin, *qkvb16, *attnb, *h2b, *hbufb, *wqkv, *wproj, *wfc1, *wfc2, *btab;
    float *x2;
    cudaGetSymbolAddress((void**)&hwin,   g_hwin_b);
    cudaGetSymbolAddress((void**)&qkvb16, g_qkv_b);
    cudaGetSymbolAddress((void**)&attnb,  g_attn_b);
    cudaGetSymbolAddress((void**)&x2,     g_x2);
    cudaGetSymbolAddress((void**)&h2b,    g_h2_b);
    cudaGetSymbolAddress((void**)&hbufb,  g_hbuf_b);
    cudaGetSymbolAddress((void**)&wqkv,   g_wqkv_b);
    cudaGetSymbolAddress((void**)&wproj,  g_wproj_b);
    cudaGetSymbolAddress((void**)&wfc1,   g_wfc1_b);
    cudaGetSymbolAddress((void**)&wfc2,   g_wfc2_b);
    cudaGetSymbolAddress((void**)&btab,   g_btab);

    static bool attr_done = false;
    if (!attr_done) {
        cudaFuncSetAttribute(gemm_mma<0>, cudaFuncAttributeMaxDynamicSharedMemorySize, GEMM_SMEM);
        cudaFuncSetAttribute(gemm_mma<1>, cudaFuncAttributeMaxDynamicSharedMemorySize, GEMM_SMEM);
        cudaFuncSetAttribute(gemm_mma<2>, cudaFuncAttributeMaxDynamicSharedMemorySize, GEMM_SMEM);
        cudaFuncSetAttribute(gemm_mma<3>, cudaFuncAttributeMaxDynamicSharedMemorySize, GEMM_SMEM);
        attr_done = true;
    }

    // 0a. fused weight conversion
    cvt4_kernel<<<(N_CVT + 255) / 256, 256>>>(qkvw, wqkv, projw, wproj,
                                              fc1w, wfc1, fc2w, wfc2);
    // 0b. combined attention bias table
    bias_prep<<<HEADS * 64, 256>>>(rpb, ridx, amask, btab);
    // 1. LN1 + shift + window partition -> bf16
    ln_kernel<true><<<TOK / 8, 256>>>(x, n1w, n1b, hwin);
    // 2. QKV GEMM -> bf16
    gemm_mma<0><<<dim3(QKVDIM / 128, TOK / 128), 256, GEMM_SMEM>>>(
        hwin, wqkv, qkvb, nullptr, nullptr, qkvb16, DIM, QKVDIM);
    // 3. windowed attention -> bf16
    attn_mma<<<2048 * HEADS, 128>>>(qkvb16, btab, attnb);
    // 4. proj GEMM + scatter + residual -> x2 (fp32)
    gemm_mma<1><<<dim3(DIM / 128, TOK / 128), 256, GEMM_SMEM>>>(
        attnb, wproj, projb, x, x2, nullptr, DIM, DIM);
    // 5. LN2 -> bf16
    ln_kernel<false><<<TOK / 8, 256>>>(x2, n2w, n2b, h2b);
    // 6. FC1 + GELU -> bf16
    gemm_mma<2><<<dim3(HIDDEN / 128, TOK / 128), 256, GEMM_SMEM>>>(
        h2b, wfc1, fc1b, nullptr, nullptr, hbufb, DIM, HIDDEN);
    // 7. FC2 + bias + residual -> final fp32
    gemm_mma<3><<<dim3(DIM / 128, TOK / 128), 256, GEMM_SMEM>>>(
        hbufb, wfc2, fc2b, x2, outp, nullptr, HIDDEN, DIM);
}

// round 15
// speedup vs baseline: 1.1673x; 1.0276x over previous
#include <cuda_runtime.h>
#include <cuda_bf16.h>
#include <math.h>
#include <stdint.h>

// ---------------------------------------------------------------------------
// Swin block: GEMMs + attention via mma.sync bf16 (fp32 accum).
// GEMMs: BM=BN=128, BK=64, 64x32/warp, 3-stage cp.async, 1 barrier/K-iter.
// Attention uses precomputed combined (rpb + shift-mask) bf16 table.
// ---------------------------------------------------------------------------

#define TOK      100352
#define DIM      256
#define HIDDEN   1024
#define QKVDIM   768
#define HEADS    8
#define HEAD_DIM 32
#define NTOK     49
#define HW       3136
#define SHIFT    3

typedef __nv_bfloat16 bf16;

// ------------------------- scratch (device globals) ------------------------
__device__ __align__(16) bf16  g_hwin_b[(size_t)TOK * DIM];
__device__ __align__(16) bf16  g_qkv_b [(size_t)TOK * QKVDIM];
__device__ __align__(16) bf16  g_attn_b[(size_t)TOK * DIM];
__device__ __align__(16) float g_x2    [(size_t)TOK * DIM];
__device__ __align__(16) bf16  g_h2_b  [(size_t)TOK * DIM];
__device__ __align__(16) bf16  g_hbuf_b[(size_t)TOK * HIDDEN];
__device__ __align__(16) bf16  g_wqkv_b [QKVDIM * DIM];
__device__ __align__(16) bf16  g_wproj_b[DIM * DIM];
__device__ __align__(16) bf16  g_wfc1_b [HIDDEN * DIM];
__device__ __align__(16) bf16  g_wfc2_b [DIM * HIDDEN];
__device__ __align__(16) bf16  g_btab  [HEADS * 64 * 64 * 64];   // 4 MB

// ------------------------------ PTX helpers --------------------------------
__device__ __forceinline__ uint32_t smem_u32(const void* p) {
    uint32_t a;
    asm("{ .reg .u64 t; cvta.to.shared.u64 t, %1; cvt.u32.u64 %0, t; }"
        : "=r"(a) : "l"(p));
    return a;
}
__device__ __forceinline__ void cp_async16(uint32_t dst, const void* src) {
    asm volatile("cp.async.cg.shared.global [%0], [%1], 16;"
                 :: "r"(dst), "l"(src));
}
#define CP_COMMIT() asm volatile("cp.async.commit_group;")
#define CP_WAIT(n)  asm volatile("cp.async.wait_group %0;" :: "n"(n))

__device__ __forceinline__ void ldsm_x4(uint32_t& r0, uint32_t& r1,
                                        uint32_t& r2, uint32_t& r3, uint32_t a) {
    asm volatile("ldmatrix.sync.aligned.m8n8.x4.shared.b16 {%0,%1,%2,%3}, [%4];"
                 : "=r"(r0), "=r"(r1), "=r"(r2), "=r"(r3) : "r"(a));
}
__device__ __forceinline__ void ldsm_x4t(uint32_t& r0, uint32_t& r1,
                                         uint32_t& r2, uint32_t& r3, uint32_t a) {
    asm volatile("ldmatrix.sync.aligned.m8n8.x4.trans.shared.b16 {%0,%1,%2,%3}, [%4];"
                 : "=r"(r0), "=r"(r1), "=r"(r2), "=r"(r3) : "r"(a));
}
__device__ __forceinline__ void mma16816(float* d, const uint32_t* a,
                                         const uint32_t* b) {
    asm volatile(
        "mma.sync.aligned.m16n8k16.row.col.f32.bf16.bf16.f32 "
        "{%0,%1,%2,%3}, {%4,%5,%6,%7}, {%8,%9}, {%0,%1,%2,%3};"
        : "+f"(d[0]), "+f"(d[1]), "+f"(d[2]), "+f"(d[3])
        : "r"(a[0]), "r"(a[1]), "r"(a[2]), "r"(a[3]), "r"(b[0]), "r"(b[1]));
}
__device__ __forceinline__ uint32_t packbf(float lo, float hi) {
    uint32_t r;
    asm("cvt.rn.bf16x2.f32 %0, %1, %2;" : "=r"(r) : "f"(hi), "f"(lo));
    return r;
}
__device__ __forceinline__ size_t scatter_dst(int row) {
    int bz = row / HW;
    int r  = row - bz * HW;
    int wI = r / NTOK;
    int t2 = r - wI * NTOK;
    int wh = wI >> 3, ww = wI & 7;
    int ii = t2 / 7,  jj = t2 - (t2 / 7) * 7;
    int sh = (wh * 7 + ii + SHIFT) % 56;
    int sw = (ww * 7 + jj + SHIFT) % 56;
    return ((size_t)bz * HW + sh * 56 + sw) * DIM;
}

// ---------------------------------------------------------------------------
// LayerNorm -> bf16, vectorized (float4 in, bf16x4 out).
// REMAP: gather with cyclic shift + window partition.
// ---------------------------------------------------------------------------
template <bool REMAP>
__global__ void ln_kernel(const float* __restrict__ in,
                          const float* __restrict__ w,
                          const float* __restrict__ b,
                          bf16* __restrict__ out)
{
    int warp = threadIdx.x >> 5;
    int lane = threadIdx.x & 31;
    int row  = blockIdx.x * 8 + warp;

    const float* src;
    if (REMAP) {
        int bz = row / HW;
        int r  = row - bz * HW;
        int wI = r / NTOK;
        int t2 = r - wI * NTOK;
        int wh = wI >> 3, ww = wI & 7;
        int i  = t2 / 7,  j  = t2 - (t2 / 7) * 7;
        int sh = (wh * 7 + i + SHIFT) % 56;
        int sw = (ww * 7 + j + SHIFT) % 56;
        src = in + ((size_t)bz * HW + sh * 56 + sw) * DIM;
    } else {
        src = in + (size_t)row * DIM;
    }

    float4 a0 = ((const float4*)src)[lane];
    float4 a1 = ((const float4*)src)[lane + 32];
    float v[8] = {a0.x, a0.y, a0.z, a0.w, a1.x, a1.y, a1.z, a1.w};
    float s = 0.f, ss = 0.f;
#pragma unroll
    for (int k = 0; k < 8; k++) { s += v[k]; ss += v[k] * v[k]; }
#pragma unroll
    for (int o = 16; o; o >>= 1) {
        s  += __shfl_xor_sync(0xffffffffu, s,  o);
        ss += __shfl_xor_sync(0xffffffffu, ss, o);
    }
    float mu   = s * (1.f / DIM);
    float var  = ss * (1.f / DIM) - mu * mu;
    float rstd = rsqrtf(var + 1e-5f);

    float4 w0 = ((const float4*)w)[lane];
    float4 w1 = ((const float4*)w)[lane + 32];
    float4 b0 = ((const float4*)b)[lane];
    float4 b1 = ((const float4*)b)[lane + 32];

    bf16* dst = out + (size_t)row * DIM;
    float h0 = (v[0] - mu) * rstd * w0.x + b0.x;
    float h1 = (v[1] - mu) * rstd * w0.y + b0.y;
    float h2 = (v[2] - mu) * rstd * w0.z + b0.z;
    float h3 = (v[3] - mu) * rstd * w0.w + b0.w;
    float h4 = (v[4] - mu) * rstd * w1.x + b1.x;
    float h5 = (v[5] - mu) * rstd * w1.y + b1.y;
    float h6 = (v[6] - mu) * rstd * w1.z + b1.z;
    float h7 = (v[7] - mu) * rstd * w1.w + b1.w;
    uint2 o0 = make_uint2(packbf(h0, h1), packbf(h2, h3));
    uint2 o1 = make_uint2(packbf(h4, h5), packbf(h6, h7));
    *(uint2*)(dst + lane * 4)       = o0;
    *(uint2*)(dst + lane * 4 + 128) = o1;
}

// ---------------------------------------------------------------------------
// Fused weight convert (4 tensors).
// ---------------------------------------------------------------------------
#define N_QKVW (QKVDIM * DIM)
#define N_PROJW (DIM * DIM)
#define N_FC1W (HIDDEN * DIM)
#define N_FC2W (DIM * HIDDEN)
#define N_CVT (N_QKVW + N_PROJW + N_FC1W + N_FC2W)

__global__ void cvt4_kernel(const float* __restrict__ s0, bf16* __restrict__ d0,
                            const float* __restrict__ s1, bf16* __restrict__ d1,
                            const float* __restrict__ s2, bf16* __restrict__ d2,
                            const float* __restrict__ s3, bf16* __restrict__ d3)
{
    int i = blockIdx.x * 256 + threadIdx.x;
    if (i < N_QKVW) {
        d0[i] = __float2bfloat16(s0[i]);
    } else if (i < N_QKVW + N_PROJW) {
        int j = i - N_QKVW;
        d1[j] = __float2bfloat16(s1[j]);
    } else if (i < N_QKVW + N_PROJW + N_FC1W) {
        int j = i - N_QKVW - N_PROJW;
        d2[j] = __float2bfloat16(s2[j]);
    } else if (i < N_CVT) {
        int j = i - N_QKVW - N_PROJW - N_FC1W;
        d3[j] = __float2bfloat16(s3[j]);
    }
}

// ---------------------------------------------------------------------------
// Combined attention bias table: btab[head][wc][i][j] (64x64 padded, bf16).
// ---------------------------------------------------------------------------
__global__ void bias_prep(const float* __restrict__ rpb,
                          const int* __restrict__ relidx,
                          const float* __restrict__ mask,
                          bf16* __restrict__ btab)
{
    int head = blockIdx.x >> 6;
    int wc   = blockIdx.x & 63;
    bf16* dst = btab + ((size_t)blockIdx.x << 12);
    for (int idx = threadIdx.x; idx < 4096; idx += 256) {
        int i = idx >> 6, j = idx & 63;
        float v = -1e30f;
        if (i < NTOK && j < NTOK) {
            int ij = i * NTOK + j;
            v = rpb[relidx[ij] * HEADS + head] + mask[wc * (NTOK * NTOK) + ij];
        }
        dst[idx] = __float2bfloat16(v);
    }
}

// ---------------------------------------------------------------------------
// bf16 mma.sync GEMM: BM=BN=128, BK=64, 256 thr, 64x32/warp, 3-stage cp.async,
// one __syncthreads per K-iter. Smem row stride 72 bf16 (conflict-free: 36r
// mod 32 = 4r covers all 8 bank-quads).
// EPI: 0 qkv(+bias->bf16) 1 proj(+bias,scatter+residual->fp32)
//      2 fc1(+bias,gelu->bf16) 3 fc2(+bias+residual->fp32)
// ---------------------------------------------------------------------------
#define STRIDE 40                                // attention tile stride
#define GST    72                                // gemm tile stride (64+8)
#define TILE_E (128 * GST)
#define GEMM_SMEM (3 * 2 * TILE_E * 2)           // 110592 bytes

template <int EPI>
__global__ void __launch_bounds__(256)
gemm_mma(const bf16* __restrict__ A, const bf16* __restrict__ W,
         const float* __restrict__ bias, const float* __restrict__ extra,
         float* __restrict__ out, bf16* __restrict__ outb,
         int K, int Ntot)
{
    extern __shared__ bf16 dsm[];
    bf16* As = dsm;                 // 3 x TILE_E
    bf16* Bs = dsm + 3 * TILE_E;    // 3 x TILE_E

    int tid    = threadIdx.x;
    int lane   = tid & 31;
    int wid    = tid >> 5;
    int warp_m = wid & 1;
    int warp_n = wid >> 1;
    int m0     = blockIdx.y * 128;
    int n0     = blockIdx.x * 128;

    int lr = tid >> 3;              // 0..31
    int lc = (tid & 7) << 3;        // 0..56

    float c[4][4][4];
#pragma unroll
    for (int i = 0; i < 4; i++)
#pragma unroll
        for (int j = 0; j < 4; j++)
#pragma unroll
            for (int k = 0; k < 4; k++) c[i][j][k] = 0.f;

    int nk = K >> 6;

    // prologue: stages 0 and 1
#pragma unroll
    for (int p = 0; p < 2; p++) {
        if (p < nk) {
            int kb = p << 6;
#pragma unroll
            for (int t = 0; t < 4; t++) {
                int r = lr + t * 32;
                cp_async16(smem_u32(As + p * TILE_E + r * GST + lc),
                           A + (size_t)(m0 + r) * K + kb + lc);
                cp_async16(smem_u32(Bs + p * TILE_E + r * GST + lc),
                           W + (size_t)(n0 + r) * K + kb + lc);
            }
        }
        CP_COMMIT();
    }

    int a_row  = warp_m * 64 + (lane & 15);
    int a_koff = (lane >> 4) << 3;
    int b_row0 = warp_n * 32 + (lane & 7) + ((lane >> 4) << 3);
    int b_koff = ((lane >> 3) & 1) << 3;

    int st = 0;
    int wr = 2;
    for (int kk = 0; kk < nk; kk++) {
        if (kk + 1 < nk) CP_WAIT(1); else CP_WAIT(0);
        __syncthreads();

        if (kk + 2 < nk) {
            int kb = (kk + 2) << 6;
#pragma unroll
            for (int t = 0; t < 4; t++) {
                int r = lr + t * 32;
                cp_async16(smem_u32(As + wr * TILE_E + r * GST + lc),
                           A + (size_t)(m0 + r) * K + kb + lc);
                cp_async16(smem_u32(Bs + wr * TILE_E + r * GST + lc),
                           W + (size_t)(n0 + r) * K + kb + lc);
            }
        }
        CP_COMMIT();

        const bf16* Ast = As + st * TILE_E;
        const bf16* Bst = Bs + st * TILE_E;
#pragma unroll
        for (int ks = 0; ks < 4; ks++) {
            uint32_t a[4][4];
            uint32_t b[4][2];
#pragma unroll
            for (int mt = 0; mt < 4; mt++)
                ldsm_x4(a[mt][0], a[mt][1], a[mt][2], a[mt][3],
                        smem_u32(Ast + (a_row + mt * 16) * GST + ks * 16 + a_koff));
#pragma unroll
            for (int np = 0; np < 2; np++)
                ldsm_x4(b[np * 2][0], b[np * 2][1], b[np * 2 + 1][0], b[np * 2 + 1][1],
                        smem_u32(Bst + (b_row0 + np * 16) * GST + ks * 16 + b_koff));
#pragma unroll
            for (int mt = 0; mt < 4; mt++)
#pragma unroll
                for (int nt = 0; nt < 4; nt++)
                    mma16816(c[mt][nt], a[mt], b[nt]);
        }
        st = (st + 1 == 3) ? 0 : st + 1;
        wr = (wr + 1 == 3) ? 0 : wr + 1;
    }

    int gid = lane >> 2;
    int qid = lane & 3;

#pragma unroll
    for (int mt = 0; mt < 4; mt++) {
        int r0 = m0 + warp_m * 64 + mt * 16 + gid;
        int r1 = r0 + 8;
        size_t base0, base1;
        if (EPI == 1) {
            base0 = scatter_dst(r0);
            base1 = scatter_dst(r1);
        } else {
            base0 = (size_t)r0 * Ntot;
            base1 = (size_t)r1 * Ntot;
        }
#pragma unroll
        for (int nt = 0; nt < 4; nt++) {
            int col = n0 + warp_n * 32 + nt * 8 + qid * 2;
            float b0 = bias[col], b1 = bias[col + 1];
            float v00 = c[mt][nt][0] + b0, v01 = c[mt][nt][1] + b1;
            float v10 = c[mt][nt][2] + b0, v11 = c[mt][nt][3] + b1;
            if (EPI == 0) {
                *(uint32_t*)(outb + base0 + col) = packbf(v00, v01);
                *(uint32_t*)(outb + base1 + col) = packbf(v10, v11);
            } else if (EPI == 1) {
                out[base0 + col]     = v00 + extra[base0 + col];
                out[base0 + col + 1] = v01 + extra[base0 + col + 1];
                out[base1 + col]     = v10 + extra[base1 + col];
                out[base1 + col + 1] = v11 + extra[base1 + col + 1];
            } else if (EPI == 2) {
                const float isq2 = 0.70710678118654752f;
                float g00 = 0.5f * v00 * (1.f + erff(v00 * isq2));
                float g01 = 0.5f * v01 * (1.f + erff(v01 * isq2));
                float g10 = 0.5f * v10 * (1.f + erff(v10 * isq2));
                float g11 = 0.5f * v11 * (1.f + erff(v11 * isq2));
                *(uint32_t*)(outb + base0 + col) = packbf(g00, g01);
                *(uint32_t*)(outb + base1 + col) = packbf(g10, g11);
            } else {
                *(float2*)(out + base0 + col) =
                    make_float2(v00 + extra[base0 + col], v01 + extra[base0 + col + 1]);
                *(float2*)(out + base1 + col) =
                    make_float2(v10 + extra[base1 + col], v11 + extra[base1 + col + 1]);
            }
        }
    }
}

// ---------------------------------------------------------------------------
// Windowed attention via mma.sync with precomputed combined bias table.
// One block per (window, head), 128 thr.
// ---------------------------------------------------------------------------
__global__ void __launch_bounds__(128)
attn_mma(const bf16* __restrict__ qkv, const bf16* __restrict__ btab,
         bf16* __restrict__ out)
{
    __shared__ bf16 qs[64][STRIDE];
    __shared__ bf16 ks[64][STRIDE];
    __shared__ bf16 vs[64][STRIDE];

    int blk  = blockIdx.x;
    int head = blk & 7;
    int win  = blk >> 3;
    int tid  = threadIdx.x;
    int lane = tid & 31;
    int warp = tid >> 5;

    for (int i = tid; i < 300; i += 128) {
        ((uint32_t*)qs)[980 + i] = 0;
        ((uint32_t*)ks)[980 + i] = 0;
        ((uint32_t*)vs)[980 + i] = 0;
    }
    const bf16* base = qkv + (size_t)win * NTOK * QKVDIM + head * HEAD_DIM;
    for (int idx = tid; idx < NTOK * 4; idx += 128) {
        int t  = idx >> 2;
        int ch = (idx & 3) << 3;
        const bf16* p = base + (size_t)t * QKVDIM + ch;
        *(uint4*)&qs[t][ch] = *(const uint4*)(p);
        *(uint4*)&ks[t][ch] = *(const uint4*)(p + 256);
        *(uint4*)&vs[t][ch] = *(const uint4*)(p + 512);
    }
    __syncthreads();

    int wm  = warp * 16;
    int gid = lane >> 2;
    int qid = lane & 3;

    uint32_t aq[2][4];
#pragma unroll
    for (int kt = 0; kt < 2; kt++)
        ldsm_x4(aq[kt][0], aq[kt][1], aq[kt][2], aq[kt][3],
                smem_u32(&qs[wm + (lane & 15)][kt * 16 + ((lane >> 4) << 3)]));

    uint32_t bk[2][8][2];
#pragma unroll
    for (int kt = 0; kt < 2; kt++)
#pragma unroll
        for (int nt2 = 0; nt2 < 4; nt2++)
            ldsm_x4(bk[kt][nt2 * 2][0], bk[kt][nt2 * 2][1],
                    bk[kt][nt2 * 2 + 1][0], bk[kt][nt2 * 2 + 1][1],
                    smem_u32(&ks[nt2 * 16 + (lane & 7) + ((lane >> 4) << 3)]
                                [kt * 16 + (((lane >> 3) & 1) << 3)]));

    float c[8][4];
#pragma unroll
    for (int nt = 0; nt < 8; nt++)
#pragma unroll
        for (int e = 0; e < 4; e++) c[nt][e] = 0.f;
#pragma unroll
    for (int kt = 0; kt < 2; kt++)
#pragma unroll
        for (int nt = 0; nt < 8; nt++)
            mma16816(c[nt], aq[kt], bk[kt][nt]);

    const float scale = 0.17677669529663687f;
    const bf16* bt = btab + (((size_t)((head << 6) | (win & 63))) << 12);
    {
        int i0 = wm + gid;
#pragma unroll
        for (int nt = 0; nt < 8; nt++) {
            int j0 = nt * 8 + qid * 2;
            uint32_t u0 = *(const uint32_t*)(bt + (i0 << 6) + j0);
            uint32_t u1 = *(const uint32_t*)(bt + ((i0 + 8) << 6) + j0);
            c[nt][0] = fmaf(c[nt][0], scale, __uint_as_float(u0 << 16));
            c[nt][1] = fmaf(c[nt][1], scale, __uint_as_float(u0 & 0xffff0000u));
            c[nt][2] = fmaf(c[nt][2], scale, __uint_as_float(u1 << 16));
            c[nt][3] = fmaf(c[nt][3], scale, __uint_as_float(u1 & 0xffff0000u));
        }
    }

    float mx0 = -1e30f, mx1 = -1e30f;
#pragma unroll
    for (int nt = 0; nt < 8; nt++) {
        mx0 = fmaxf(mx0, fmaxf(c[nt][0], c[nt][1]));
        mx1 = fmaxf(mx1, fmaxf(c[nt][2], c[nt][3]));
    }
#pragma unroll
    for (int o = 1; o <= 2; o <<= 1) {
        mx0 = fmaxf(mx0, __shfl_xor_sync(0xffffffffu, mx0, o));
        mx1 = fmaxf(mx1, __shfl_xor_sync(0xffffffffu, mx1, o));
    }
    float s0 = 0.f, s1 = 0.f;
#pragma unroll
    for (int nt = 0; nt < 8; nt++) {
        c[nt][0] = __expf(c[nt][0] - mx0); s0 += c[nt][0];
        c[nt][1] = __expf(c[nt][1] - mx0); s0 += c[nt][1];
        c[nt][2] = __expf(c[nt][2] - mx1); s1 += c[nt][2];
        c[nt][3] = __expf(c[nt][3] - mx1); s1 += c[nt][3];
    }
#pragma unroll
    for (int o = 1; o <= 2; o <<= 1) {
        s0 += __shfl_xor_sync(0xffffffffu, s0, o);
        s1 += __shfl_xor_sync(0xffffffffu, s1, o);
    }
    float inv0 = 1.f / s0, inv1 = 1.f / s1;
#pragma unroll
    for (int nt = 0; nt < 8; nt++) {
        c[nt][0] *= inv0; c[nt][1] *= inv0;
        c[nt][2] *= inv1; c[nt][3] *= inv1;
    }

    uint32_t ap[4][4];
#pragma unroll
    for (int kt = 0; kt < 4; kt++) {
        ap[kt][0] = packbf(c[2 * kt][0],     c[2 * kt][1]);
        ap[kt][1] = packbf(c[2 * kt][2],     c[2 * kt][3]);
        ap[kt][2] = packbf(c[2 * kt + 1][0], c[2 * kt + 1][1]);
        ap[kt][3] = packbf(c[2 * kt + 1][2], c[2 * kt + 1][3]);
    }

    float o[4][4];
#pragma unroll
    for (int nt = 0; nt < 4; nt++)
#pragma unroll
        for (int e = 0; e < 4; e++) o[nt][e] = 0.f;
#pragma unroll
    for (int kt = 0; kt < 4; kt++) {
#pragma unroll
        for (int ng = 0; ng < 2; ng++) {
            uint32_t r0, r1, r2, r3;
            ldsm_x4t(r0, r1, r2, r3,
                smem_u32(&vs[kt * 16 + (lane & 7) + (((lane >> 3) & 1) << 3)]
                            [ng * 16 + ((lane >> 4) << 3)]));
            uint32_t bv0[2] = {r0, r1};
            uint32_t bv1[2] = {r2, r3};
            mma16816(o[ng * 2],     ap[kt], bv0);
            mma16816(o[ng * 2 + 1], ap[kt], bv1);
        }
    }

    int i0 = wm + gid;
    int i1 = i0 + 8;
    size_t ob0 = ((size_t)win * NTOK + i0) * DIM + head * HEAD_DIM;
    size_t ob1 = ((size_t)win * NTOK + i1) * DIM + head * HEAD_DIM;
#pragma unroll
    for (int nt = 0; nt < 4; nt++) {
        int n = nt * 8 + qid * 2;
        if (i0 < NTOK) *(uint32_t*)(out + ob0 + n) = packbf(o[nt][0], o[nt][1]);
        if (i1 < NTOK) *(uint32_t*)(out + ob1 + n) = packbf(o[nt][2], o[nt][3]);
    }
}

// ---------------------------------------------------------------------------
extern "C" void kernel_launch(void* const* d_in, const int* in_sizes, int n_in,
                              void* d_out, int out_size)
{
    const float* x     = (const float*)d_in[0];
    const float* n1w   = (const float*)d_in[1];
    const float* n1b   = (const float*)d_in[2];
    const float* qkvw  = (const float*)d_in[3];
    const float* qkvb  = (const float*)d_in[4];
    const float* rpb   = (const float*)d_in[5];
    const float* projw = (const float*)d_in[6];
    const float* projb = (const float*)d_in[7];
    const float* n2w   = (const float*)d_in[8];
    const float* n2b   = (const float*)d_in[9];
    const float* fc1w  = (const float*)d_in[10];
    const float* fc1b  = (const float*)d_in[11];
    const float* fc2w  = (const float*)d_in[12];
    const float* fc2b  = (const float*)d_in[13];
    const int*   ridx  = (const int*)d_in[14];
    const float* amask = (const float*)d_in[15];
    float* outp = (float*)d_out;

    bf16 *hwin, *qkvb16, *attnb, *h2b, *hbufb, *wqkv, *wproj, *wfc1, *wfc2, *btab;
    float *x2;
    cudaGetSymbolAddress((void**)&hwin,   g_hwin_b);
    cudaGetSymbolAddress((void**)&qkvb16, g_qkv_b);
    cudaGetSymbolAddress((void**)&attnb,  g_attn_b);
    cudaGetSymbolAddress((void**)&x2,     g_x2);
    cudaGetSymbolAddress((void**)&h2b,    g_h2_b);
    cudaGetSymbolAddress((void**)&hbufb,  g_hbuf_b);
    cudaGetSymbolAddress((void**)&wqkv,   g_wqkv_b);
    cudaGetSymbolAddress((void**)&wproj,  g_wproj_b);
    cudaGetSymbolAddress((void**)&wfc1,   g_wfc1_b);
    cudaGetSymbolAddress((void**)&wfc2,   g_wfc2_b);
    cudaGetSymbolAddress((void**)&btab,   g_btab);

    static bool attr_done = false;
    if (!attr_done) {
        cudaFuncSetAttribute(gemm_mma<0>, cudaFuncAttributeMaxDynamicSharedMemorySize, GEMM_SMEM);
        cudaFuncSetAttribute(gemm_mma<1>, cudaFuncAttributeMaxDynamicSharedMemorySize, GEMM_SMEM);
        cudaFuncSetAttribute(gemm_mma<2>, cudaFuncAttributeMaxDynamicSharedMemorySize, GEMM_SMEM);
        cudaFuncSetAttribute(gemm_mma<3>, cudaFuncAttributeMaxDynamicSharedMemorySize, GEMM_SMEM);
        attr_done = true;
    }

    // 0a. fused weight conversion
    cvt4_kernel<<<(N_CVT + 255) / 256, 256>>>(qkvw, wqkv, projw, wproj,
                                              fc1w, wfc1, fc2w, wfc2);
    // 0b. combined attention bias table
    bias_prep<<<HEADS * 64, 256>>>(rpb, ridx, amask, btab);
    // 1. LN1 + shift + window partition -> bf16
    ln_kernel<true><<<TOK / 8, 256>>>(x, n1w, n1b, hwin);
    // 2. QKV GEMM -> bf16
    gemm_mma<0><<<dim3(QKVDIM / 128, TOK / 128), 256, GEMM_SMEM>>>(
        hwin, wqkv, qkvb, nullptr, nullptr, qkvb16, DIM, QKVDIM);
    // 3. windowed attention -> bf16
    attn_mma<<<2048 * HEADS, 128>>>(qkvb16, btab, attnb);
    // 4. proj GEMM + scatter + residual -> x2 (fp32)
    gemm_mma<1><<<dim3(DIM / 128, TOK / 128), 256, GEMM_SMEM>>>(
        attnb, wproj, projb, x, x2, nullptr, DIM, DIM);
    // 5. LN2 -> bf16
    ln_kernel<false><<<TOK / 8, 256>>>(x2, n2w, n2b, h2b);
    // 6. FC1 + GELU -> bf16
    gemm_mma<2><<<dim3(HIDDEN / 128, TOK / 128), 256, GEMM_SMEM>>>(
        h2b, wfc1, fc1b, nullptr, nullptr, hbufb, DIM, HIDDEN);
    // 7. FC2 + bias + residual -> final fp32
    gemm_mma<3><<<dim3(DIM / 128, TOK / 128), 256, GEMM_SMEM>>>(
        hbufb, wfc2, fc2b, x2, outp, nullptr, HIDDEN, DIM);
}